// round 4
// baseline (speedup 1.0000x reference)
#include <cuda_runtime.h>
#include <cuda_fp16.h>
#include <cstdint>

#define NN   100000
#define EE   1600000
#define ETOT (EE + NN)
#define GG   64
#define NB_SCAN 98   // ceil(NN/1024)

// ---------------- scratch (device globals: no allocation allowed) ----------------
__device__ __align__(16) int   g_cnt[NN];
__device__ __align__(16) int   g_excl[NN];
__device__ __align__(16) int   g_bsum[128];
__device__ __align__(16) int   g_rowoff[NN + 1];
__device__ __align__(16) int   g_cur[NN];
__device__ __align__(16) int   g_csr[ETOT];

__device__ __align__(16) float   g_h[NN * 64];    // fp32 h (for score kernel)
__device__ __align__(16) __half2 g_hh[NN * 32];   // fp16 h (for edge gathers)
__device__ __align__(16) float   g_buf[NN * 64];  // conv output (next layer input)
__device__ __align__(16) float   g_ssrc[NN * 8];
__device__ __align__(16) float   g_sdst[NN * 8];
__device__ __align__(16) float   g_h4[NN * 4];
__device__ __align__(16) float   g_o4[NN * 4];
__device__ __align__(16) float   g_pool[GG * 4];
__device__ __align__(16) float   g_cnt_g[GG];
__device__ int g_shift;   // 0: indices are int32; 1: indices are int64 (read low words)

// ---------------- f32x2 helpers ----------------
__device__ __forceinline__ void fma2(unsigned long long& d, unsigned long long a,
                                     unsigned long long b) {
    asm("fma.rn.f32x2 %0, %1, %2, %0;" : "+l"(d) : "l"(a), "l"(b));
}
__device__ __forceinline__ unsigned long long pack2(float x) {
    unsigned long long r;
    asm("mov.b64 %0, {%1, %1};" : "=l"(r) : "f"(x));
    return r;
}
__device__ __forceinline__ float2 unpk2(unsigned long long v) {
    float2 f;
    asm("mov.b64 {%0, %1}, %2;" : "=f"(f.x), "=f"(f.y) : "l"(v));
    return f;
}

// ---------------- dtype detection ----------------
__global__ void detect_kernel(const unsigned int* __restrict__ w) {
    __shared__ int any;
    if (threadIdx.x == 0) any = 0;
    __syncthreads();
    unsigned int acc = 0;
#pragma unroll
    for (int k = 0; k < 8; k++) {
        long long pos = 1LL + 2LL * ((long long)(threadIdx.x * 8 + k) * 391LL);
        if (pos < 2LL * EE) acc |= w[pos];
    }
    if (acc) atomicOr(&any, 1);
    __syncthreads();
    if (threadIdx.x == 0) g_shift = any ? 0 : 1;
}

// ---------------- CSR build ----------------
__global__ void zero_kernel() {
    int i = blockIdx.x * blockDim.x + threadIdx.x;
    if (i < NN) g_cnt[i] = 0;
    if (i < GG * 4) g_pool[i] = 0.f;
    if (i < GG) g_cnt_g[i] = 0.f;
}

__global__ void count_kernel(const int* __restrict__ ei) {
    int i = blockIdx.x * blockDim.x + threadIdx.x;
    if (i >= ETOT) return;
    int sh = g_shift;
    int dst = (i < EE) ? ei[((long long)(EE + i)) << sh] : (i - EE);
    atomicAdd(&g_cnt[dst], 1);
}

__global__ void scan1_kernel() {
    __shared__ int shm[1024];
    int tid = threadIdx.x;
    int gid = blockIdx.x * 1024 + tid;
    int v = (gid < NN) ? g_cnt[gid] : 0;
    shm[tid] = v;
    __syncthreads();
#pragma unroll
    for (int off = 1; off < 1024; off <<= 1) {
        int t = (tid >= off) ? shm[tid - off] : 0;
        __syncthreads();
        shm[tid] += t;
        __syncthreads();
    }
    if (gid < NN) g_excl[gid] = shm[tid] - v;
    if (tid == 1023) g_bsum[blockIdx.x] = shm[tid];
}

__global__ void scan2_kernel() {
    __shared__ int shm[128];
    int tid = threadIdx.x;
    int v = (tid < NB_SCAN) ? g_bsum[tid] : 0;
    shm[tid] = v;
    __syncthreads();
#pragma unroll
    for (int off = 1; off < 128; off <<= 1) {
        int t = (tid >= off) ? shm[tid - off] : 0;
        __syncthreads();
        shm[tid] += t;
        __syncthreads();
    }
    g_bsum[tid] = shm[tid] - v;  // exclusive
}

__global__ void scan3_kernel() {
    int gid = blockIdx.x * blockDim.x + threadIdx.x;
    if (gid < NN) {
        int off = g_excl[gid] + g_bsum[gid >> 10];
        g_rowoff[gid] = off;
        g_cur[gid]    = off;
    }
    if (gid == 0) g_rowoff[NN] = ETOT;
}

__global__ void scatter_kernel(const int* __restrict__ ei) {
    int i = blockIdx.x * blockDim.x + threadIdx.x;
    if (i >= ETOT) return;
    int sh = g_shift;
    int src, dst;
    if (i < EE) {
        src = ei[((long long)i) << sh];
        dst = ei[((long long)(EE + i)) << sh];
    } else {
        src = dst = i - EE;
    }
    int p = atomicAdd(&g_cur[dst], 1);
    g_csr[p] = src;
}

// ---------------- GEMMs ----------------
// conv1: [N,4] @ [4,64] -> g_h (fp32) + g_hh (fp16). Thread = one feature pair.
__global__ void conv1_gemm(const float* __restrict__ x, const float* __restrict__ W) {
    int idx = blockIdx.x * blockDim.x + threadIdx.x;
    if (idx >= NN * 32) return;
    int n = idx >> 5, p = idx & 31;
    float4 xr = *reinterpret_cast<const float4*>(x + n * 4);
    float s0 = xr.x * W[2 * p]     + xr.y * W[64 + 2 * p]
             + xr.z * W[128 + 2 * p] + xr.w * W[192 + 2 * p];
    float s1 = xr.x * W[2 * p + 1]     + xr.y * W[64 + 2 * p + 1]
             + xr.z * W[128 + 2 * p + 1] + xr.w * W[192 + 2 * p + 1];
    *reinterpret_cast<float2*>(g_h + n * 64 + 2 * p) = make_float2(s0, s1);
    g_hh[idx] = __floats2half2_rn(s0, s1);
}

// g_buf [N,64] @ W [64,64] -> g_h + g_hh.
// Block = 64 nodes, 256 threads; thread = 2 nodes x 8 feats; packed f32x2 FMA.
// X tile stored transposed [k][node] with stride 68 (conflict-free LDS.64).
__global__ void gemm64_kernel(const float* __restrict__ W) {
    __shared__ float Ws[64 * 64];
    __shared__ float Xt[64 * 68];
    int tx = threadIdx.x;
    int n0 = blockIdx.x * 64;
    const float4* W4p = reinterpret_cast<const float4*>(W);
    float4* Ws4 = reinterpret_cast<float4*>(Ws);
#pragma unroll
    for (int i = tx; i < 1024; i += 256) Ws4[i] = W4p[i];
    const float4* in4 = reinterpret_cast<const float4*>(g_buf);
#pragma unroll
    for (int i = tx; i < 1024; i += 256) {
        int r = i >> 4, c = i & 15;
        float4 v = make_float4(0.f, 0.f, 0.f, 0.f);
        if (n0 + r < NN) v = in4[(n0 + r) * 16 + c];
        Xt[(4 * c + 0) * 68 + r] = v.x;
        Xt[(4 * c + 1) * 68 + r] = v.y;
        Xt[(4 * c + 2) * 68 + r] = v.z;
        Xt[(4 * c + 3) * 68 + r] = v.w;
    }
    __syncthreads();
    int fg = tx & 7;    // features fg*8 .. +7
    int ng = tx >> 3;   // nodes n0 + ng*2, +1
    unsigned long long acc[2][4];
#pragma unroll
    for (int i = 0; i < 2; i++)
#pragma unroll
        for (int j = 0; j < 4; j++) acc[i][j] = 0ull;
#pragma unroll 4
    for (int k = 0; k < 64; k++) {
        ulonglong2 wA = *reinterpret_cast<const ulonglong2*>(&Ws[k * 64 + fg * 8]);
        ulonglong2 wB = *reinterpret_cast<const ulonglong2*>(&Ws[k * 64 + fg * 8 + 4]);
        float2 xv = *reinterpret_cast<const float2*>(&Xt[k * 68 + ng * 2]);
        unsigned long long x0 = pack2(xv.x);
        unsigned long long x1 = pack2(xv.y);
        fma2(acc[0][0], wA.x, x0); fma2(acc[0][1], wA.y, x0);
        fma2(acc[0][2], wB.x, x0); fma2(acc[0][3], wB.y, x0);
        fma2(acc[1][0], wA.x, x1); fma2(acc[1][1], wA.y, x1);
        fma2(acc[1][2], wB.x, x1); fma2(acc[1][3], wB.y, x1);
    }
#pragma unroll
    for (int i = 0; i < 2; i++) {
        int n = n0 + ng * 2 + i;
        if (n < NN) {
            float2 p0 = unpk2(acc[i][0]);
            float2 p1 = unpk2(acc[i][1]);
            float2 p2 = unpk2(acc[i][2]);
            float2 p3 = unpk2(acc[i][3]);
            float4* op = reinterpret_cast<float4*>(g_h + n * 64 + fg * 8);
            op[0] = make_float4(p0.x, p0.y, p1.x, p1.y);
            op[1] = make_float4(p2.x, p2.y, p3.x, p3.y);
            __half2* hh = g_hh + n * 32 + fg * 4;
            hh[0] = __floats2half2_rn(p0.x, p0.y);
            hh[1] = __floats2half2_rn(p1.x, p1.y);
            hh[2] = __floats2half2_rn(p2.x, p2.y);
            hh[3] = __floats2half2_rn(p3.x, p3.y);
        }
    }
}

// conv4: g_buf [N,64] @ W [64,4] -> g_h4, warp per node
__global__ void conv4_gemm(const float* __restrict__ W) {
    int gtid = blockIdx.x * blockDim.x + threadIdx.x;
    int node = gtid >> 5;
    int lane = gtid & 31;
    if (node >= NN) return;
    float v0 = g_buf[node * 64 + lane];
    float v1 = g_buf[node * 64 + 32 + lane];
    float4 wA = reinterpret_cast<const float4*>(W)[lane];
    float4 wB = reinterpret_cast<const float4*>(W)[lane + 32];
    float p0 = v0 * wA.x + v1 * wB.x;
    float p1 = v0 * wA.y + v1 * wB.y;
    float p2 = v0 * wA.z + v1 * wB.z;
    float p3 = v0 * wA.w + v1 * wB.w;
#pragma unroll
    for (int off = 16; off > 0; off >>= 1) {
        p0 += __shfl_xor_sync(0xffffffffu, p0, off);
        p1 += __shfl_xor_sync(0xffffffffu, p1, off);
        p2 += __shfl_xor_sync(0xffffffffu, p2, off);
        p3 += __shfl_xor_sync(0xffffffffu, p3, off);
    }
    if (lane == 0) {
        float4* op = reinterpret_cast<float4*>(g_h4 + node * 4);
        *op = make_float4(p0, p1, p2, p3);
    }
}

// ---------------- attention scores s_src/s_dst (fp32 h) ----------------
template <int H, int C, bool LAYER4>
__global__ void s_kernel(const float* __restrict__ a_src, const float* __restrict__ a_dst) {
    int idx = blockIdx.x * blockDim.x + threadIdx.x;
    if (idx >= NN * H) return;
    int node = idx / H;
    int head = idx % H;
    const float* hsrc = LAYER4 ? g_h4 : g_h;
    const float* hp = hsrc + node * (H * C) + head * C;
    const float* as = a_src + head * C;
    const float* ad = a_dst + head * C;
    float s1 = 0.f, s2 = 0.f;
#pragma unroll
    for (int c = 0; c < C; c++) {
        float v = hp[c];
        s1 += v * as[c];
        s2 += v * ad[c];
    }
    g_ssrc[idx] = s1;
    g_sdst[idx] = s2;
}

// ---------------- segment-softmax aggregation (CSR, warp-group per node) -------
// FPL==2 path (layers 1-3): gathers fp16 h rows (128B/edge). Layer4: fp32.
template <int H, int C, int LPN, int FPL, bool DO_ELU, bool LAYER4>
__global__ void agg_kernel(const float* __restrict__ bias) {
    const int lane = threadIdx.x & 31;
    const int warp = (blockIdx.x * blockDim.x + threadIdx.x) >> 5;
    const int npw = 32 / LPN;
    const int node = warp * npw + lane / LPN;
    if (node >= NN) return;
    float* __restrict__ out = LAYER4 ? g_o4 : g_buf;
    const int gl = lane % LPN;
    const int f0 = gl * FPL;
    const int head = f0 / C;   // with FPL=2 both features share the head (f0 even)
    const float sd = g_sdst[node * H + head];
    const int rs = g_rowoff[node];
    const int re = g_rowoff[node + 1];
    float den = 0.f, a0 = 0.f, a1 = 0.f;
    int src = (rs < re) ? g_csr[rs] : 0;
    for (int e = rs; e < re; ++e) {
        int nsrc = (e + 1 < re) ? g_csr[e + 1] : 0;
        float s = g_ssrc[src * H + head] + sd;
        s = (s > 0.f) ? s : 0.2f * s;                  // leaky_relu(0.2)
        float ex = __expf(s);                          // max-shift dropped: exact ratio
        den += ex;
        if (FPL == 2) {
            float2 hv = __half22float2(g_hh[src * 32 + gl]);
            a0 += ex * hv.x;
            a1 += ex * hv.y;
        } else {
            a0 += ex * g_h4[src * (H * C) + f0];
        }
        src = nsrc;
    }
    float inv = 1.f / (den + 1e-16f);
    float o0 = a0 * inv + bias[f0];
    if (DO_ELU) o0 = (o0 > 0.f) ? o0 : (__expf(o0) - 1.f);
    out[node * (H * C) + f0] = o0;
    if (FPL == 2) {
        float o1 = a1 * inv + bias[f0 + 1];
        if (DO_ELU) o1 = (o1 > 0.f) ? o1 : (__expf(o1) - 1.f);
        out[node * (H * C) + f0 + 1] = o1;
    }
}

// ---------------- pooling + head ----------------
__global__ void pool_kernel(const int* __restrict__ batch) {
    int i = blockIdx.x * blockDim.x + threadIdx.x;
    int lane = threadIdx.x & 31;
    int sh = g_shift;
    int g = -1;
    float v0 = 0.f, v1 = 0.f, v2 = 0.f, v3 = 0.f;
    if (i < NN) {
        g = batch[((long long)i) << sh];
        float4 hv = *reinterpret_cast<const float4*>(g_o4 + i * 4);
        v0 = hv.x; v1 = hv.y; v2 = hv.z; v3 = hv.w;
    }
    int g0 = __shfl_sync(0xffffffffu, g, 0);
    bool uniform = __all_sync(0xffffffffu, g == g0);
    if (uniform && g0 >= 0) {
#pragma unroll
        for (int off = 16; off > 0; off >>= 1) {
            v0 += __shfl_xor_sync(0xffffffffu, v0, off);
            v1 += __shfl_xor_sync(0xffffffffu, v1, off);
            v2 += __shfl_xor_sync(0xffffffffu, v2, off);
            v3 += __shfl_xor_sync(0xffffffffu, v3, off);
        }
        if (lane == 0) {
            atomicAdd(&g_pool[g0 * 4 + 0], v0);
            atomicAdd(&g_pool[g0 * 4 + 1], v1);
            atomicAdd(&g_pool[g0 * 4 + 2], v2);
            atomicAdd(&g_pool[g0 * 4 + 3], v3);
            atomicAdd(&g_cnt_g[g0], 32.f);
        }
    } else if (i < NN) {
        atomicAdd(&g_pool[g * 4 + 0], v0);
        atomicAdd(&g_pool[g * 4 + 1], v1);
        atomicAdd(&g_pool[g * 4 + 2], v2);
        atomicAdd(&g_pool[g * 4 + 3], v3);
        atomicAdd(&g_cnt_g[g], 1.f);
    }
}

__global__ void final_kernel(const float* __restrict__ Wl, const float* __restrict__ bl,
                             float* __restrict__ out) {
    int g = threadIdx.x;
    if (g >= GG) return;
    float c = fmaxf(g_cnt_g[g], 1.f);
    float s = 0.f;
#pragma unroll
    for (int f = 0; f < 4; f++) s += (g_pool[g * 4 + f] / c) * Wl[f];
    out[g] = s + bl[0];
}

// ---------------- launch ----------------
extern "C" void kernel_launch(void* const* d_in, const int* in_sizes, int n_in,
                              void* d_out, int out_size) {
    const float* x      = (const float*)d_in[0];
    const int*   ei     = (const int*)d_in[1];
    const int*   batch  = (const int*)d_in[2];
    const float* W1     = (const float*)d_in[3];
    const float* a_src1 = (const float*)d_in[4];
    const float* a_dst1 = (const float*)d_in[5];
    const float* b1     = (const float*)d_in[6];
    const float* W2     = (const float*)d_in[7];
    const float* a_src2 = (const float*)d_in[8];
    const float* a_dst2 = (const float*)d_in[9];
    const float* b2     = (const float*)d_in[10];
    const float* W4     = (const float*)d_in[11];
    const float* a_src4 = (const float*)d_in[12];
    const float* a_dst4 = (const float*)d_in[13];
    const float* b4     = (const float*)d_in[14];
    const float* Wl     = (const float*)d_in[15];
    const float* bl     = (const float*)d_in[16];
    float* out = (float*)d_out;

    const int B = 256;
    detect_kernel<<<1, 1024>>>((const unsigned int*)ei);
    // CSR build
    zero_kernel<<<(NN + B - 1) / B, B>>>();
    count_kernel<<<(ETOT + B - 1) / B, B>>>(ei);
    scan1_kernel<<<NB_SCAN, 1024>>>();
    scan2_kernel<<<1, 128>>>();
    scan3_kernel<<<(NN + B - 1) / B, B>>>();
    scatter_kernel<<<(ETOT + B - 1) / B, B>>>(ei);

    const int gridWarpPerNode = (NN * 32 + B - 1) / B;   // 12500

    // conv1 (H=8, C=8) + ELU
    conv1_gemm<<<(NN * 32 + B - 1) / B, B>>>(x, W1);
    s_kernel<8, 8, false><<<(NN * 8 + B - 1) / B, B>>>(a_src1, a_dst1);
    agg_kernel<8, 8, 32, 2, true, false><<<gridWarpPerNode, B>>>(b1);

    // conv2 (H=1, C=64), applied twice
    gemm64_kernel<<<(NN + 63) / 64, B>>>(W2);
    s_kernel<1, 64, false><<<(NN + B - 1) / B, B>>>(a_src2, a_dst2);
    agg_kernel<1, 64, 32, 2, false, false><<<gridWarpPerNode, B>>>(b2);

    gemm64_kernel<<<(NN + 63) / 64, B>>>(W2);
    s_kernel<1, 64, false><<<(NN + B - 1) / B, B>>>(a_src2, a_dst2);
    agg_kernel<1, 64, 32, 2, false, false><<<gridWarpPerNode, B>>>(b2);

    // conv4 (H=1, C=4)
    conv4_gemm<<<gridWarpPerNode, B>>>(W4);
    s_kernel<1, 4, true><<<(NN + B - 1) / B, B>>>(a_src4, a_dst4);
    agg_kernel<1, 4, 4, 1, false, true><<<(NN * 4 + B - 1) / B, B>>>(b4);

    // global mean pool + linear head
    pool_kernel<<<(NN + B - 1) / B, B>>>(batch);
    final_kernel<<<1, 64>>>(Wl, bl, out);
}

// round 6
// speedup vs baseline: 1.1475x; 1.1475x over previous
#include <cuda_runtime.h>
#include <cstdint>

#define NN   100000
#define EE   1600000
#define ETOT (EE + NN)
#define GG   64
#define NB_SCAN 98   // ceil(NN/1024)

// ---------------- scratch (device globals: no allocation allowed) ----------------
__device__ __align__(16) int   g_cnt[NN];
__device__ __align__(16) int   g_excl[NN];
__device__ __align__(16) int   g_bsum[128];
__device__ __align__(16) int   g_rowoff[NN + 1];
__device__ __align__(16) int   g_cur[NN];
__device__ __align__(16) int   g_csr[ETOT];

__device__ __align__(16) float g_h[NN * 64];     // GEMM output (gathered by edges)
__device__ __align__(16) float g_buf[NN * 64];   // conv output (next layer input)
__device__ __align__(16) float g_ssrc[NN * 8];
__device__ __align__(16) float g_sdst[NN * 8];
__device__ __align__(16) float g_h4[NN * 4];
__device__ __align__(16) float g_o4[NN * 4];
__device__ __align__(16) float g_pool[GG * 4];
__device__ __align__(16) float g_cnt_g[GG];
__device__ int g_shift;   // 0: indices are int32; 1: indices are int64 (read low words)

// ---------------- dtype detection ----------------
__global__ void detect_kernel(const unsigned int* __restrict__ w) {
    __shared__ int any;
    if (threadIdx.x == 0) any = 0;
    __syncthreads();
    unsigned int acc = 0;
#pragma unroll
    for (int k = 0; k < 8; k++) {
        long long pos = 1LL + 2LL * ((long long)(threadIdx.x * 8 + k) * 391LL);
        if (pos < 2LL * EE) acc |= w[pos];
    }
    if (acc) atomicOr(&any, 1);
    __syncthreads();
    if (threadIdx.x == 0) g_shift = any ? 0 : 1;
}

// ---------------- CSR build ----------------
__global__ void zero_kernel() {
    int i = blockIdx.x * blockDim.x + threadIdx.x;
    if (i < NN) g_cnt[i] = 0;
    if (i < GG * 4) g_pool[i] = 0.f;
    if (i < GG) g_cnt_g[i] = 0.f;
}

__global__ void count_kernel(const int* __restrict__ ei) {
    int i = blockIdx.x * blockDim.x + threadIdx.x;
    if (i >= ETOT) return;
    int sh = g_shift;
    int dst = (i < EE) ? ei[((long long)(EE + i)) << sh] : (i - EE);
    atomicAdd(&g_cnt[dst], 1);
}

__global__ void scan1_kernel() {
    __shared__ int shm[1024];
    int tid = threadIdx.x;
    int gid = blockIdx.x * 1024 + tid;
    int v = (gid < NN) ? g_cnt[gid] : 0;
    shm[tid] = v;
    __syncthreads();
#pragma unroll
    for (int off = 1; off < 1024; off <<= 1) {
        int t = (tid >= off) ? shm[tid - off] : 0;
        __syncthreads();
        shm[tid] += t;
        __syncthreads();
    }
    if (gid < NN) g_excl[gid] = shm[tid] - v;
    if (tid == 1023) g_bsum[blockIdx.x] = shm[tid];
}

__global__ void scan2_kernel() {
    __shared__ int shm[128];
    int tid = threadIdx.x;
    int v = (tid < NB_SCAN) ? g_bsum[tid] : 0;
    shm[tid] = v;
    __syncthreads();
#pragma unroll
    for (int off = 1; off < 128; off <<= 1) {
        int t = (tid >= off) ? shm[tid - off] : 0;
        __syncthreads();
        shm[tid] += t;
        __syncthreads();
    }
    g_bsum[tid] = shm[tid] - v;  // exclusive
}

__global__ void scan3_kernel() {
    int gid = blockIdx.x * blockDim.x + threadIdx.x;
    if (gid < NN) {
        int off = g_excl[gid] + g_bsum[gid >> 10];
        g_rowoff[gid] = off;
        g_cur[gid]    = off;
    }
    if (gid == 0) g_rowoff[NN] = ETOT;
}

__global__ void scatter_kernel(const int* __restrict__ ei) {
    int i = blockIdx.x * blockDim.x + threadIdx.x;
    if (i >= ETOT) return;
    int sh = g_shift;
    int src, dst;
    if (i < EE) {
        src = ei[((long long)i) << sh];
        dst = ei[((long long)(EE + i)) << sh];
    } else {
        src = dst = i - EE;
    }
    int p = atomicAdd(&g_cur[dst], 1);
    g_csr[p] = src;
}

// ---------------- GEMMs ----------------
// conv1: [N,4] @ [4,64] -> g_h
__global__ void conv1_gemm(const float* __restrict__ x, const float* __restrict__ W) {
    int idx = blockIdx.x * blockDim.x + threadIdx.x;
    if (idx >= NN * 64) return;
    int n = idx >> 6, f = idx & 63;
    float s = 0.f;
#pragma unroll
    for (int k = 0; k < 4; k++) s += x[n * 4 + k] * W[k * 64 + f];
    g_h[idx] = s;
}

// g_buf [N,64] @ W [64,64] -> g_h. Block = 128 nodes, 256 threads, thread = 4 nodes x 8 feats.
// X tile uses additive column swizzle col'=(col+row)&63: zero extra smem,
// conflict-free per-k reads (rows spaced 4 -> distinct banks). Total smem = 48KB exactly.
__global__ void gemm64_kernel(const float* __restrict__ W) {
    __shared__ float Ws[64 * 64];
    __shared__ float Xs[128 * 64];
    int tx = threadIdx.x;
    int n0 = blockIdx.x * 128;
    const float4* W4p = reinterpret_cast<const float4*>(W);
    float4* Ws4 = reinterpret_cast<float4*>(Ws);
#pragma unroll
    for (int i = tx; i < 1024; i += 256) Ws4[i] = W4p[i];
    const float4* in4 = reinterpret_cast<const float4*>(g_buf);
#pragma unroll
    for (int i = tx; i < 2048; i += 256) {
        int r = i >> 4, c = i & 15;
        float4 v = make_float4(0.f, 0.f, 0.f, 0.f);
        if (n0 + r < NN) v = in4[(n0 + r) * 16 + c];
        Xs[r * 64 + ((4 * c + 0 + r) & 63)] = v.x;
        Xs[r * 64 + ((4 * c + 1 + r) & 63)] = v.y;
        Xs[r * 64 + ((4 * c + 2 + r) & 63)] = v.z;
        Xs[r * 64 + ((4 * c + 3 + r) & 63)] = v.w;
    }
    __syncthreads();
    int fg = tx & 7;    // feature group: f = fg*8 .. +7
    int ng = tx >> 3;   // node group: n = n0 + ng*4 .. +3
    float acc[4][8];
#pragma unroll
    for (int i = 0; i < 4; i++)
#pragma unroll
        for (int j = 0; j < 8; j++) acc[i][j] = 0.f;
#pragma unroll 8
    for (int k = 0; k < 64; k++) {
        float4 w0 = Ws4[k * 16 + fg * 2];
        float4 w1 = Ws4[k * 16 + fg * 2 + 1];
#pragma unroll
        for (int i = 0; i < 4; i++) {
            int row = ng * 4 + i;
            float xv = Xs[row * 64 + ((k + row) & 63)];
            acc[i][0] += xv * w0.x; acc[i][1] += xv * w0.y;
            acc[i][2] += xv * w0.z; acc[i][3] += xv * w0.w;
            acc[i][4] += xv * w1.x; acc[i][5] += xv * w1.y;
            acc[i][6] += xv * w1.z; acc[i][7] += xv * w1.w;
        }
    }
#pragma unroll
    for (int i = 0; i < 4; i++) {
        int n = n0 + ng * 4 + i;
        if (n < NN) {
            float4* op = reinterpret_cast<float4*>(g_h + n * 64 + fg * 8);
            op[0] = make_float4(acc[i][0], acc[i][1], acc[i][2], acc[i][3]);
            op[1] = make_float4(acc[i][4], acc[i][5], acc[i][6], acc[i][7]);
        }
    }
}

// conv4: g_buf [N,64] @ W [64,4] -> g_h4, warp per node
__global__ void conv4_gemm(const float* __restrict__ W) {
    int gtid = blockIdx.x * blockDim.x + threadIdx.x;
    int node = gtid >> 5;
    int lane = gtid & 31;
    if (node >= NN) return;
    float v0 = g_buf[node * 64 + lane];
    float v1 = g_buf[node * 64 + 32 + lane];
    float4 wA = reinterpret_cast<const float4*>(W)[lane];
    float4 wB = reinterpret_cast<const float4*>(W)[lane + 32];
    float p0 = v0 * wA.x + v1 * wB.x;
    float p1 = v0 * wA.y + v1 * wB.y;
    float p2 = v0 * wA.z + v1 * wB.z;
    float p3 = v0 * wA.w + v1 * wB.w;
#pragma unroll
    for (int off = 16; off > 0; off >>= 1) {
        p0 += __shfl_xor_sync(0xffffffffu, p0, off);
        p1 += __shfl_xor_sync(0xffffffffu, p1, off);
        p2 += __shfl_xor_sync(0xffffffffu, p2, off);
        p3 += __shfl_xor_sync(0xffffffffu, p3, off);
    }
    if (lane == 0) {
        float4* op = reinterpret_cast<float4*>(g_h4 + node * 4);
        *op = make_float4(p0, p1, p2, p3);
    }
}

// ---------------- attention scores s_src/s_dst ----------------
template <int H, int C, bool LAYER4>
__global__ void s_kernel(const float* __restrict__ a_src, const float* __restrict__ a_dst) {
    int idx = blockIdx.x * blockDim.x + threadIdx.x;
    if (idx >= NN * H) return;
    int node = idx / H;
    int head = idx % H;
    const float* hsrc = LAYER4 ? g_h4 : g_h;
    const float* hp = hsrc + node * (H * C) + head * C;
    const float* as = a_src + head * C;
    const float* ad = a_dst + head * C;
    float s1 = 0.f, s2 = 0.f;
#pragma unroll
    for (int c = 0; c < C; c++) {
        float v = hp[c];
        s1 += v * as[c];
        s2 += v * ad[c];
    }
    g_ssrc[idx] = s1;
    g_sdst[idx] = s2;
}

// ---------------- segment-softmax aggregation (CSR, warp-group per node) -------
// LPN lanes per node; lane owns FPL consecutive features. Edge loop unrolled x4
// with batched loads to expose MLP (latency-bound fix).
template <int H, int C, int LPN, int FPL, bool DO_ELU, bool LAYER4>
__global__ void agg_kernel(const float* __restrict__ bias) {
    const int lane = threadIdx.x & 31;
    const int warp = (blockIdx.x * blockDim.x + threadIdx.x) >> 5;
    const int npw = 32 / LPN;
    const int node = warp * npw + lane / LPN;
    if (node >= NN) return;
    const float* __restrict__ h = LAYER4 ? g_h4 : g_h;
    float* __restrict__ out = LAYER4 ? g_o4 : g_buf;
    const int gl = lane % LPN;
    const int f0 = gl * FPL;
    const int head = f0 / C;
    const float sd = g_sdst[node * H + head];
    const int rs = g_rowoff[node];
    const int re = g_rowoff[node + 1];
    float den = 0.f, a0 = 0.f, a1 = 0.f;
    int e = rs;
    for (; e + 4 <= re; e += 4) {
        // batch all loads first -> MLP
        int s0 = g_csr[e], s1 = g_csr[e + 1], s2 = g_csr[e + 2], s3 = g_csr[e + 3];
        float t0 = g_ssrc[s0 * H + head];
        float t1 = g_ssrc[s1 * H + head];
        float t2 = g_ssrc[s2 * H + head];
        float t3 = g_ssrc[s3 * H + head];
        float2 v0, v1, v2, v3;
        if (FPL == 2) {
            v0 = *reinterpret_cast<const float2*>(h + s0 * (H * C) + f0);
            v1 = *reinterpret_cast<const float2*>(h + s1 * (H * C) + f0);
            v2 = *reinterpret_cast<const float2*>(h + s2 * (H * C) + f0);
            v3 = *reinterpret_cast<const float2*>(h + s3 * (H * C) + f0);
        } else {
            v0.x = h[s0 * (H * C) + f0]; v0.y = 0.f;
            v1.x = h[s1 * (H * C) + f0]; v1.y = 0.f;
            v2.x = h[s2 * (H * C) + f0]; v2.y = 0.f;
            v3.x = h[s3 * (H * C) + f0]; v3.y = 0.f;
        }
        t0 += sd; t1 += sd; t2 += sd; t3 += sd;
        t0 = (t0 > 0.f) ? t0 : 0.2f * t0;
        t1 = (t1 > 0.f) ? t1 : 0.2f * t1;
        t2 = (t2 > 0.f) ? t2 : 0.2f * t2;
        t3 = (t3 > 0.f) ? t3 : 0.2f * t3;
        float e0 = __expf(t0), e1 = __expf(t1), e2 = __expf(t2), e3 = __expf(t3);
        den += (e0 + e1) + (e2 + e3);
        a0 += e0 * v0.x + e1 * v1.x + e2 * v2.x + e3 * v3.x;
        if (FPL == 2) a1 += e0 * v0.y + e1 * v1.y + e2 * v2.y + e3 * v3.y;
    }
    for (; e < re; ++e) {
        int src = g_csr[e];
        float s = g_ssrc[src * H + head] + sd;
        s = (s > 0.f) ? s : 0.2f * s;
        float ex = __expf(s);
        den += ex;
        if (FPL == 2) {
            float2 hv = *reinterpret_cast<const float2*>(h + src * (H * C) + f0);
            a0 += ex * hv.x;
            a1 += ex * hv.y;
        } else {
            a0 += ex * h[src * (H * C) + f0];
        }
    }
    float inv = 1.f / (den + 1e-16f);
    float o0 = a0 * inv + bias[f0];
    if (DO_ELU) o0 = (o0 > 0.f) ? o0 : (__expf(o0) - 1.f);
    out[node * (H * C) + f0] = o0;
    if (FPL == 2) {
        float o1 = a1 * inv + bias[f0 + 1];
        if (DO_ELU) o1 = (o1 > 0.f) ? o1 : (__expf(o1) - 1.f);
        out[node * (H * C) + f0 + 1] = o1;
    }
}

// ---------------- pooling + head ----------------
__global__ void pool_kernel(const int* __restrict__ batch) {
    int i = blockIdx.x * blockDim.x + threadIdx.x;
    int lane = threadIdx.x & 31;
    int sh = g_shift;
    int g = -1;
    float v0 = 0.f, v1 = 0.f, v2 = 0.f, v3 = 0.f;
    if (i < NN) {
        g = batch[((long long)i) << sh];
        float4 hv = *reinterpret_cast<const float4*>(g_o4 + i * 4);
        v0 = hv.x; v1 = hv.y; v2 = hv.z; v3 = hv.w;
    }
    int g0 = __shfl_sync(0xffffffffu, g, 0);
    bool uniform = __all_sync(0xffffffffu, g == g0);
    if (uniform && g0 >= 0) {
#pragma unroll
        for (int off = 16; off > 0; off >>= 1) {
            v0 += __shfl_xor_sync(0xffffffffu, v0, off);
            v1 += __shfl_xor_sync(0xffffffffu, v1, off);
            v2 += __shfl_xor_sync(0xffffffffu, v2, off);
            v3 += __shfl_xor_sync(0xffffffffu, v3, off);
        }
        if (lane == 0) {
            atomicAdd(&g_pool[g0 * 4 + 0], v0);
            atomicAdd(&g_pool[g0 * 4 + 1], v1);
            atomicAdd(&g_pool[g0 * 4 + 2], v2);
            atomicAdd(&g_pool[g0 * 4 + 3], v3);
            atomicAdd(&g_cnt_g[g0], 32.f);
        }
    } else if (i < NN) {
        atomicAdd(&g_pool[g * 4 + 0], v0);
        atomicAdd(&g_pool[g * 4 + 1], v1);
        atomicAdd(&g_pool[g * 4 + 2], v2);
        atomicAdd(&g_pool[g * 4 + 3], v3);
        atomicAdd(&g_cnt_g[g], 1.f);
    }
}

__global__ void final_kernel(const float* __restrict__ Wl, const float* __restrict__ bl,
                             float* __restrict__ out) {
    int g = threadIdx.x;
    if (g >= GG) return;
    float c = fmaxf(g_cnt_g[g], 1.f);
    float s = 0.f;
#pragma unroll
    for (int f = 0; f < 4; f++) s += (g_pool[g * 4 + f] / c) * Wl[f];
    out[g] = s + bl[0];
}

// ---------------- launch ----------------
extern "C" void kernel_launch(void* const* d_in, const int* in_sizes, int n_in,
                              void* d_out, int out_size) {
    const float* x      = (const float*)d_in[0];
    const int*   ei     = (const int*)d_in[1];
    const int*   batch  = (const int*)d_in[2];
    const float* W1     = (const float*)d_in[3];
    const float* a_src1 = (const float*)d_in[4];
    const float* a_dst1 = (const float*)d_in[5];
    const float* b1     = (const float*)d_in[6];
    const float* W2     = (const float*)d_in[7];
    const float* a_src2 = (const float*)d_in[8];
    const float* a_dst2 = (const float*)d_in[9];
    const float* b2     = (const float*)d_in[10];
    const float* W4     = (const float*)d_in[11];
    const float* a_src4 = (const float*)d_in[12];
    const float* a_dst4 = (const float*)d_in[13];
    const float* b4     = (const float*)d_in[14];
    const float* Wl     = (const float*)d_in[15];
    const float* bl     = (const float*)d_in[16];
    float* out = (float*)d_out;

    const int B = 256;
    detect_kernel<<<1, 1024>>>((const unsigned int*)ei);
    // CSR build
    zero_kernel<<<(NN + B - 1) / B, B>>>();
    count_kernel<<<(ETOT + B - 1) / B, B>>>(ei);
    scan1_kernel<<<NB_SCAN, 1024>>>();
    scan2_kernel<<<1, 128>>>();
    scan3_kernel<<<(NN + B - 1) / B, B>>>();
    scatter_kernel<<<(ETOT + B - 1) / B, B>>>(ei);

    const int gridWarpPerNode = (NN * 32 + B - 1) / B;   // 12500

    // conv1 (H=8, C=8) + ELU
    conv1_gemm<<<(NN * 64 + B - 1) / B, B>>>(x, W1);
    s_kernel<8, 8, false><<<(NN * 8 + B - 1) / B, B>>>(a_src1, a_dst1);
    agg_kernel<8, 8, 32, 2, true, false><<<gridWarpPerNode, B>>>(b1);

    // conv2 (H=1, C=64), applied twice
    gemm64_kernel<<<(NN + 127) / 128, B>>>(W2);
    s_kernel<1, 64, false><<<(NN + B - 1) / B, B>>>(a_src2, a_dst2);
    agg_kernel<1, 64, 32, 2, false, false><<<gridWarpPerNode, B>>>(b2);

    gemm64_kernel<<<(NN + 127) / 128, B>>>(W2);
    s_kernel<1, 64, false><<<(NN + B - 1) / B, B>>>(a_src2, a_dst2);
    agg_kernel<1, 64, 32, 2, false, false><<<gridWarpPerNode, B>>>(b2);

    // conv4 (H=1, C=4)
    conv4_gemm<<<gridWarpPerNode, B>>>(W4);
    s_kernel<1, 4, true><<<(NN + B - 1) / B, B>>>(a_src4, a_dst4);
    agg_kernel<1, 4, 4, 1, false, true><<<(NN * 4 + B - 1) / B, B>>>(b4);

    // global mean pool + linear head
    pool_kernel<<<(NN + B - 1) / B, B>>>(batch);
    final_kernel<<<1, 64>>>(Wl, bl, out);
}

// round 7
// speedup vs baseline: 1.1515x; 1.0035x over previous
#include <cuda_runtime.h>
#include <cuda_fp16.h>
#include <cstdint>

#define NN   100000
#define EE   1600000
#define ETOT (EE + NN)
#define GG   64
#define NB_SCAN 98   // ceil(NN/1024)

// ---------------- scratch (device globals: no allocation allowed) ----------------
__device__ __align__(16) int   g_cnt[NN];
__device__ __align__(16) int   g_excl[NN];
__device__ __align__(16) int   g_bsum[128];
__device__ __align__(16) int   g_rowoff[NN + 1];
__device__ __align__(16) int   g_cur[NN];
__device__ __align__(16) int   g_csr[ETOT];

__device__ __align__(16) float   g_h[NN * 64];    // fp32 h (scores + layer-4 path)
__device__ __align__(16) __half2 g_hh[NN * 32];   // fp16 h (edge gathers, layers 1-3)
__device__ __align__(16) float   g_buf[NN * 64];  // conv output (next layer input)
__device__ __align__(16) float   g_ssrc[NN * 8];
__device__ __align__(16) float   g_sdst[NN * 8];
__device__ __align__(16) float   g_h4[NN * 4];
__device__ __align__(16) float   g_o4[NN * 4];
__device__ __align__(16) float   g_pool[GG * 4];
__device__ __align__(16) float   g_cnt_g[GG];
__device__ int g_shift;   // 0: indices are int32; 1: indices are int64 (read low words)

// ---------------- dtype detection ----------------
__global__ void detect_kernel(const unsigned int* __restrict__ w) {
    __shared__ int any;
    if (threadIdx.x == 0) any = 0;
    __syncthreads();
    unsigned int acc = 0;
#pragma unroll
    for (int k = 0; k < 8; k++) {
        long long pos = 1LL + 2LL * ((long long)(threadIdx.x * 8 + k) * 391LL);
        if (pos < 2LL * EE) acc |= w[pos];
    }
    if (acc) atomicOr(&any, 1);
    __syncthreads();
    if (threadIdx.x == 0) g_shift = any ? 0 : 1;
}

// ---------------- CSR build ----------------
__global__ void zero_kernel() {
    int i = blockIdx.x * blockDim.x + threadIdx.x;
    if (i < NN) g_cnt[i] = 0;
    if (i < GG * 4) g_pool[i] = 0.f;
    if (i < GG) g_cnt_g[i] = 0.f;
}

__global__ void count_kernel(const int* __restrict__ ei) {
    int i = blockIdx.x * blockDim.x + threadIdx.x;
    if (i >= ETOT) return;
    int sh = g_shift;
    int dst = (i < EE) ? ei[((long long)(EE + i)) << sh] : (i - EE);
    atomicAdd(&g_cnt[dst], 1);
}

__global__ void scan1_kernel() {
    __shared__ int shm[1024];
    int tid = threadIdx.x;
    int gid = blockIdx.x * 1024 + tid;
    int v = (gid < NN) ? g_cnt[gid] : 0;
    shm[tid] = v;
    __syncthreads();
#pragma unroll
    for (int off = 1; off < 1024; off <<= 1) {
        int t = (tid >= off) ? shm[tid - off] : 0;
        __syncthreads();
        shm[tid] += t;
        __syncthreads();
    }
    if (gid < NN) g_excl[gid] = shm[tid] - v;
    if (tid == 1023) g_bsum[blockIdx.x] = shm[tid];
}

__global__ void scan2_kernel() {
    __shared__ int shm[128];
    int tid = threadIdx.x;
    int v = (tid < NB_SCAN) ? g_bsum[tid] : 0;
    shm[tid] = v;
    __syncthreads();
#pragma unroll
    for (int off = 1; off < 128; off <<= 1) {
        int t = (tid >= off) ? shm[tid - off] : 0;
        __syncthreads();
        shm[tid] += t;
        __syncthreads();
    }
    g_bsum[tid] = shm[tid] - v;  // exclusive
}

__global__ void scan3_kernel() {
    int gid = blockIdx.x * blockDim.x + threadIdx.x;
    if (gid < NN) {
        int off = g_excl[gid] + g_bsum[gid >> 10];
        g_rowoff[gid] = off;
        g_cur[gid]    = off;
    }
    if (gid == 0) g_rowoff[NN] = ETOT;
}

__global__ void scatter_kernel(const int* __restrict__ ei) {
    int i = blockIdx.x * blockDim.x + threadIdx.x;
    if (i >= ETOT) return;
    int sh = g_shift;
    int src, dst;
    if (i < EE) {
        src = ei[((long long)i) << sh];
        dst = ei[((long long)(EE + i)) << sh];
    } else {
        src = dst = i - EE;
    }
    int p = atomicAdd(&g_cur[dst], 1);
    g_csr[p] = src;
}

// ---------------- GEMMs ----------------
// conv1: [N,4] @ [4,64] -> g_h (fp32) + g_hh (fp16). Thread = one feature pair.
__global__ void conv1_gemm(const float* __restrict__ x, const float* __restrict__ W) {
    int idx = blockIdx.x * blockDim.x + threadIdx.x;
    if (idx >= NN * 32) return;
    int n = idx >> 5, p = idx & 31;
    float4 xr = *reinterpret_cast<const float4*>(x + n * 4);
    float s0 = xr.x * W[2 * p]       + xr.y * W[64 + 2 * p]
             + xr.z * W[128 + 2 * p] + xr.w * W[192 + 2 * p];
    float s1 = xr.x * W[2 * p + 1]       + xr.y * W[64 + 2 * p + 1]
             + xr.z * W[128 + 2 * p + 1] + xr.w * W[192 + 2 * p + 1];
    *reinterpret_cast<float2*>(g_h + n * 64 + 2 * p) = make_float2(s0, s1);
    g_hh[idx] = __floats2half2_rn(s0, s1);
}

// g_buf [N,64] @ W [64,64] -> g_h + g_hh. Block = 128 nodes, 256 threads,
// thread = 4 nodes x 8 feats. X tile: additive swizzle col'=(col+row)&63,
// conflict-free, 48KB smem exactly.
__global__ void gemm64_kernel(const float* __restrict__ W) {
    __shared__ float Ws[64 * 64];
    __shared__ float Xs[128 * 64];
    int tx = threadIdx.x;
    int n0 = blockIdx.x * 128;
    const float4* W4p = reinterpret_cast<const float4*>(W);
    float4* Ws4 = reinterpret_cast<float4*>(Ws);
#pragma unroll
    for (int i = tx; i < 1024; i += 256) Ws4[i] = W4p[i];
    const float4* in4 = reinterpret_cast<const float4*>(g_buf);
#pragma unroll
    for (int i = tx; i < 2048; i += 256) {
        int r = i >> 4, c = i & 15;
        float4 v = make_float4(0.f, 0.f, 0.f, 0.f);
        if (n0 + r < NN) v = in4[(n0 + r) * 16 + c];
        Xs[r * 64 + ((4 * c + 0 + r) & 63)] = v.x;
        Xs[r * 64 + ((4 * c + 1 + r) & 63)] = v.y;
        Xs[r * 64 + ((4 * c + 2 + r) & 63)] = v.z;
        Xs[r * 64 + ((4 * c + 3 + r) & 63)] = v.w;
    }
    __syncthreads();
    int fg = tx & 7;    // feature group: f = fg*8 .. +7
    int ng = tx >> 3;   // node group: n = n0 + ng*4 .. +3
    float acc[4][8];
#pragma unroll
    for (int i = 0; i < 4; i++)
#pragma unroll
        for (int j = 0; j < 8; j++) acc[i][j] = 0.f;
#pragma unroll 8
    for (int k = 0; k < 64; k++) {
        float4 w0 = Ws4[k * 16 + fg * 2];
        float4 w1 = Ws4[k * 16 + fg * 2 + 1];
#pragma unroll
        for (int i = 0; i < 4; i++) {
            int row = ng * 4 + i;
            float xv = Xs[row * 64 + ((k + row) & 63)];
            acc[i][0] += xv * w0.x; acc[i][1] += xv * w0.y;
            acc[i][2] += xv * w0.z; acc[i][3] += xv * w0.w;
            acc[i][4] += xv * w1.x; acc[i][5] += xv * w1.y;
            acc[i][6] += xv * w1.z; acc[i][7] += xv * w1.w;
        }
    }
#pragma unroll
    for (int i = 0; i < 4; i++) {
        int n = n0 + ng * 4 + i;
        if (n < NN) {
            float4* op = reinterpret_cast<float4*>(g_h + n * 64 + fg * 8);
            op[0] = make_float4(acc[i][0], acc[i][1], acc[i][2], acc[i][3]);
            op[1] = make_float4(acc[i][4], acc[i][5], acc[i][6], acc[i][7]);
            __half2* hh = g_hh + n * 32 + fg * 4;
            hh[0] = __floats2half2_rn(acc[i][0], acc[i][1]);
            hh[1] = __floats2half2_rn(acc[i][2], acc[i][3]);
            hh[2] = __floats2half2_rn(acc[i][4], acc[i][5]);
            hh[3] = __floats2half2_rn(acc[i][6], acc[i][7]);
        }
    }
}

// conv4: g_buf [N,64] @ W [64,4] -> g_h4, warp per node
__global__ void conv4_gemm(const float* __restrict__ W) {
    int gtid = blockIdx.x * blockDim.x + threadIdx.x;
    int node = gtid >> 5;
    int lane = gtid & 31;
    if (node >= NN) return;
    float v0 = g_buf[node * 64 + lane];
    float v1 = g_buf[node * 64 + 32 + lane];
    float4 wA = reinterpret_cast<const float4*>(W)[lane];
    float4 wB = reinterpret_cast<const float4*>(W)[lane + 32];
    float p0 = v0 * wA.x + v1 * wB.x;
    float p1 = v0 * wA.y + v1 * wB.y;
    float p2 = v0 * wA.z + v1 * wB.z;
    float p3 = v0 * wA.w + v1 * wB.w;
#pragma unroll
    for (int off = 16; off > 0; off >>= 1) {
        p0 += __shfl_xor_sync(0xffffffffu, p0, off);
        p1 += __shfl_xor_sync(0xffffffffu, p1, off);
        p2 += __shfl_xor_sync(0xffffffffu, p2, off);
        p3 += __shfl_xor_sync(0xffffffffu, p3, off);
    }
    if (lane == 0) {
        float4* op = reinterpret_cast<float4*>(g_h4 + node * 4);
        *op = make_float4(p0, p1, p2, p3);
    }
}

// ---------------- attention scores s_src/s_dst (fp32 h) ----------------
template <int H, int C, bool LAYER4>
__global__ void s_kernel(const float* __restrict__ a_src, const float* __restrict__ a_dst) {
    int idx = blockIdx.x * blockDim.x + threadIdx.x;
    if (idx >= NN * H) return;
    int node = idx / H;
    int head = idx % H;
    const float* hsrc = LAYER4 ? g_h4 : g_h;
    const float* hp = hsrc + node * (H * C) + head * C;
    const float* as = a_src + head * C;
    const float* ad = a_dst + head * C;
    float s1 = 0.f, s2 = 0.f;
#pragma unroll
    for (int c = 0; c < C; c++) {
        float v = hp[c];
        s1 += v * as[c];
        s2 += v * ad[c];
    }
    g_ssrc[idx] = s1;
    g_sdst[idx] = s2;
}

// ---------------- segment-softmax aggregation (CSR, warp-group per node) -------
// Layers 1-3 (FPL==2): gathers fp16 g_hh (4B/lane, 128B/edge). Layer 4: fp32.
// Edge loop unrolled x4 with batched loads (MLP).
template <int H, int C, int LPN, int FPL, bool DO_ELU, bool LAYER4>
__global__ void agg_kernel(const float* __restrict__ bias) {
    const int lane = threadIdx.x & 31;
    const int warp = (blockIdx.x * blockDim.x + threadIdx.x) >> 5;
    const int npw = 32 / LPN;
    const int node = warp * npw + lane / LPN;
    if (node >= NN) return;
    float* __restrict__ out = LAYER4 ? g_o4 : g_buf;
    const int gl = lane % LPN;
    const int f0 = gl * FPL;
    const int head = f0 / C;
    const float sd = g_sdst[node * H + head];
    const int rs = g_rowoff[node];
    const int re = g_rowoff[node + 1];
    float den = 0.f, a0 = 0.f, a1 = 0.f;
    int e = rs;
    for (; e + 4 <= re; e += 4) {
        int s0 = g_csr[e], s1 = g_csr[e + 1], s2 = g_csr[e + 2], s3 = g_csr[e + 3];
        float t0 = g_ssrc[s0 * H + head];
        float t1 = g_ssrc[s1 * H + head];
        float t2 = g_ssrc[s2 * H + head];
        float t3 = g_ssrc[s3 * H + head];
        float2 v0, v1, v2, v3;
        if (FPL == 2) {
            v0 = __half22float2(g_hh[s0 * 32 + gl]);
            v1 = __half22float2(g_hh[s1 * 32 + gl]);
            v2 = __half22float2(g_hh[s2 * 32 + gl]);
            v3 = __half22float2(g_hh[s3 * 32 + gl]);
        } else {
            v0.x = g_h4[s0 * (H * C) + f0]; v0.y = 0.f;
            v1.x = g_h4[s1 * (H * C) + f0]; v1.y = 0.f;
            v2.x = g_h4[s2 * (H * C) + f0]; v2.y = 0.f;
            v3.x = g_h4[s3 * (H * C) + f0]; v3.y = 0.f;
        }
        t0 += sd; t1 += sd; t2 += sd; t3 += sd;
        t0 = (t0 > 0.f) ? t0 : 0.2f * t0;
        t1 = (t1 > 0.f) ? t1 : 0.2f * t1;
        t2 = (t2 > 0.f) ? t2 : 0.2f * t2;
        t3 = (t3 > 0.f) ? t3 : 0.2f * t3;
        float e0 = __expf(t0), e1 = __expf(t1), e2 = __expf(t2), e3 = __expf(t3);
        den += (e0 + e1) + (e2 + e3);
        a0 += e0 * v0.x + e1 * v1.x + e2 * v2.x + e3 * v3.x;
        if (FPL == 2) a1 += e0 * v0.y + e1 * v1.y + e2 * v2.y + e3 * v3.y;
    }
    for (; e < re; ++e) {
        int src = g_csr[e];
        float s = g_ssrc[src * H + head] + sd;
        s = (s > 0.f) ? s : 0.2f * s;
        float ex = __expf(s);
        den += ex;
        if (FPL == 2) {
            float2 hv = __half22float2(g_hh[src * 32 + gl]);
            a0 += ex * hv.x;
            a1 += ex * hv.y;
        } else {
            a0 += ex * g_h4[src * (H * C) + f0];
        }
    }
    float inv = 1.f / (den + 1e-16f);
    float o0 = a0 * inv + bias[f0];
    if (DO_ELU) o0 = (o0 > 0.f) ? o0 : (__expf(o0) - 1.f);
    out[node * (H * C) + f0] = o0;
    if (FPL == 2) {
        float o1 = a1 * inv + bias[f0 + 1];
        if (DO_ELU) o1 = (o1 > 0.f) ? o1 : (__expf(o1) - 1.f);
        out[node * (H * C) + f0 + 1] = o1;
    }
}

// ---------------- pooling + head ----------------
__global__ void pool_kernel(const int* __restrict__ batch) {
    int i = blockIdx.x * blockDim.x + threadIdx.x;
    int lane = threadIdx.x & 31;
    int sh = g_shift;
    int g = -1;
    float v0 = 0.f, v1 = 0.f, v2 = 0.f, v3 = 0.f;
    if (i < NN) {
        g = batch[((long long)i) << sh];
        float4 hv = *reinterpret_cast<const float4*>(g_o4 + i * 4);
        v0 = hv.x; v1 = hv.y; v2 = hv.z; v3 = hv.w;
    }
    int g0 = __shfl_sync(0xffffffffu, g, 0);
    bool uniform = __all_sync(0xffffffffu, g == g0);
    if (uniform && g0 >= 0) {
#pragma unroll
        for (int off = 16; off > 0; off >>= 1) {
            v0 += __shfl_xor_sync(0xffffffffu, v0, off);
            v1 += __shfl_xor_sync(0xffffffffu, v1, off);
            v2 += __shfl_xor_sync(0xffffffffu, v2, off);
            v3 += __shfl_xor_sync(0xffffffffu, v3, off);
        }
        if (lane == 0) {
            atomicAdd(&g_pool[g0 * 4 + 0], v0);
            atomicAdd(&g_pool[g0 * 4 + 1], v1);
            atomicAdd(&g_pool[g0 * 4 + 2], v2);
            atomicAdd(&g_pool[g0 * 4 + 3], v3);
            atomicAdd(&g_cnt_g[g0], 32.f);
        }
    } else if (i < NN) {
        atomicAdd(&g_pool[g * 4 + 0], v0);
        atomicAdd(&g_pool[g * 4 + 1], v1);
        atomicAdd(&g_pool[g * 4 + 2], v2);
        atomicAdd(&g_pool[g * 4 + 3], v3);
        atomicAdd(&g_cnt_g[g], 1.f);
    }
}

__global__ void final_kernel(const float* __restrict__ Wl, const float* __restrict__ bl,
                             float* __restrict__ out) {
    int g = threadIdx.x;
    if (g >= GG) return;
    float c = fmaxf(g_cnt_g[g], 1.f);
    float s = 0.f;
#pragma unroll
    for (int f = 0; f < 4; f++) s += (g_pool[g * 4 + f] / c) * Wl[f];
    out[g] = s + bl[0];
}

// ---------------- launch ----------------
extern "C" void kernel_launch(void* const* d_in, const int* in_sizes, int n_in,
                              void* d_out, int out_size) {
    const float* x      = (const float*)d_in[0];
    const int*   ei     = (const int*)d_in[1];
    const int*   batch  = (const int*)d_in[2];
    const float* W1     = (const float*)d_in[3];
    const float* a_src1 = (const float*)d_in[4];
    const float* a_dst1 = (const float*)d_in[5];
    const float* b1     = (const float*)d_in[6];
    const float* W2     = (const float*)d_in[7];
    const float* a_src2 = (const float*)d_in[8];
    const float* a_dst2 = (const float*)d_in[9];
    const float* b2     = (const float*)d_in[10];
    const float* W4     = (const float*)d_in[11];
    const float* a_src4 = (const float*)d_in[12];
    const float* a_dst4 = (const float*)d_in[13];
    const float* b4     = (const float*)d_in[14];
    const float* Wl     = (const float*)d_in[15];
    const float* bl     = (const float*)d_in[16];
    float* out = (float*)d_out;

    const int B = 256;
    detect_kernel<<<1, 1024>>>((const unsigned int*)ei);
    // CSR build
    zero_kernel<<<(NN + B - 1) / B, B>>>();
    count_kernel<<<(ETOT + B - 1) / B, B>>>(ei);
    scan1_kernel<<<NB_SCAN, 1024>>>();
    scan2_kernel<<<1, 128>>>();
    scan3_kernel<<<(NN + B - 1) / B, B>>>();
    scatter_kernel<<<(ETOT + B - 1) / B, B>>>(ei);

    const int gridWarpPerNode = (NN * 32 + B - 1) / B;   // 12500

    // conv1 (H=8, C=8) + ELU
    conv1_gemm<<<(NN * 32 + B - 1) / B, B>>>(x, W1);
    s_kernel<8, 8, false><<<(NN * 8 + B - 1) / B, B>>>(a_src1, a_dst1);
    agg_kernel<8, 8, 32, 2, true, false><<<gridWarpPerNode, B>>>(b1);

    // conv2 (H=1, C=64), applied twice
    gemm64_kernel<<<(NN + 127) / 128, B>>>(W2);
    s_kernel<1, 64, false><<<(NN + B - 1) / B, B>>>(a_src2, a_dst2);
    agg_kernel<1, 64, 32, 2, false, false><<<gridWarpPerNode, B>>>(b2);

    gemm64_kernel<<<(NN + 127) / 128, B>>>(W2);
    s_kernel<1, 64, false><<<(NN + B - 1) / B, B>>>(a_src2, a_dst2);
    agg_kernel<1, 64, 32, 2, false, false><<<gridWarpPerNode, B>>>(b2);

    // conv4 (H=1, C=4)
    conv4_gemm<<<gridWarpPerNode, B>>>(W4);
    s_kernel<1, 4, true><<<(NN + B - 1) / B, B>>>(a_src4, a_dst4);
    agg_kernel<1, 4, 4, 1, false, true><<<(NN * 4 + B - 1) / B, B>>>(b4);

    // global mean pool + linear head
    pool_kernel<<<(NN + B - 1) / B, B>>>(batch);
    final_kernel<<<1, 64>>>(Wl, bl, out);
}

// round 8
// speedup vs baseline: 1.2114x; 1.0520x over previous
#include <cuda_runtime.h>
#include <cuda_fp16.h>
#include <cstdint>

#define NN   100000
#define EE   1600000
#define ETOT (EE + NN)
#define GG   64
#define NB_SCAN 98   // ceil(NN/1024)

// ---------------- scratch (device globals: no allocation allowed) ----------------
__device__ __align__(16) int   g_cnt[NN];
__device__ __align__(16) int   g_excl[NN];
__device__ __align__(16) int   g_bsum[128];
__device__ __align__(16) int   g_rowoff[NN + 1];
__device__ __align__(16) int   g_cur[NN];
__device__ __align__(16) int   g_csr[ETOT];

__device__ __align__(16) float   g_h[NN * 64];    // fp32 h (layer-4 gathers)
__device__ __align__(16) __half2 g_hh[NN * 32];   // fp16 h (edge gathers, layers 1-3)
__device__ __align__(16) float   g_buf[NN * 64];  // conv output (next layer input)
__device__ __align__(16) float   g_ssrc[NN * 8];
__device__ __align__(16) float   g_sdst[NN * 8];
__device__ __align__(16) float   g_h4[NN * 4];
__device__ __align__(16) float   g_o4[NN * 4];
__device__ __align__(16) float   g_pool[GG * 4];
__device__ __align__(16) float   g_cnt_g[GG];
__device__ int g_shift;   // 0: indices are int32; 1: indices are int64 (read low words)

// ---------------- dtype detection ----------------
__global__ void detect_kernel(const unsigned int* __restrict__ w) {
    __shared__ int any;
    if (threadIdx.x == 0) any = 0;
    __syncthreads();
    unsigned int acc = 0;
#pragma unroll
    for (int k = 0; k < 8; k++) {
        long long pos = 1LL + 2LL * ((long long)(threadIdx.x * 8 + k) * 391LL);
        if (pos < 2LL * EE) acc |= w[pos];
    }
    if (acc) atomicOr(&any, 1);
    __syncthreads();
    if (threadIdx.x == 0) g_shift = any ? 0 : 1;
}

// ---------------- CSR build ----------------
__global__ void zero_kernel() {
    int i = blockIdx.x * blockDim.x + threadIdx.x;
    if (i < NN) g_cnt[i] = 0;
    if (i < GG * 4) g_pool[i] = 0.f;
    if (i < GG) g_cnt_g[i] = 0.f;
}

__global__ void count_kernel(const int* __restrict__ ei) {
    int i = blockIdx.x * blockDim.x + threadIdx.x;
    if (i >= ETOT) return;
    int sh = g_shift;
    int dst = (i < EE) ? ei[((long long)(EE + i)) << sh] : (i - EE);
    atomicAdd(&g_cnt[dst], 1);
}

__global__ void scan1_kernel() {
    __shared__ int shm[1024];
    int tid = threadIdx.x;
    int gid = blockIdx.x * 1024 + tid;
    int v = (gid < NN) ? g_cnt[gid] : 0;
    shm[tid] = v;
    __syncthreads();
#pragma unroll
    for (int off = 1; off < 1024; off <<= 1) {
        int t = (tid >= off) ? shm[tid - off] : 0;
        __syncthreads();
        shm[tid] += t;
        __syncthreads();
    }
    if (gid < NN) g_excl[gid] = shm[tid] - v;
    if (tid == 1023) g_bsum[blockIdx.x] = shm[tid];
}

__global__ void scan2_kernel() {
    __shared__ int shm[128];
    int tid = threadIdx.x;
    int v = (tid < NB_SCAN) ? g_bsum[tid] : 0;
    shm[tid] = v;
    __syncthreads();
#pragma unroll
    for (int off = 1; off < 128; off <<= 1) {
        int t = (tid >= off) ? shm[tid - off] : 0;
        __syncthreads();
        shm[tid] += t;
        __syncthreads();
    }
    g_bsum[tid] = shm[tid] - v;  // exclusive
}

__global__ void scan3_kernel() {
    int gid = blockIdx.x * blockDim.x + threadIdx.x;
    if (gid < NN) {
        int off = g_excl[gid] + g_bsum[gid >> 10];
        g_rowoff[gid] = off;
        g_cur[gid]    = off;
    }
    if (gid == 0) g_rowoff[NN] = ETOT;
}

__global__ void scatter_kernel(const int* __restrict__ ei) {
    int i = blockIdx.x * blockDim.x + threadIdx.x;
    if (i >= ETOT) return;
    int sh = g_shift;
    int src, dst;
    if (i < EE) {
        src = ei[((long long)i) << sh];
        dst = ei[((long long)(EE + i)) << sh];
    } else {
        src = dst = i - EE;
    }
    int p = atomicAdd(&g_cur[dst], 1);
    g_csr[p] = src;
}

// ---------------- GEMMs (with fused attention-score epilogues) ----------------
// conv1: [N,4] @ [4,64] -> g_h + g_hh + fused s_src/s_dst (H=8, C=8).
// Warp per node, lane p owns features 2p, 2p+1; head = p>>2 (4 lanes per head).
__global__ void conv1_gemm(const float* __restrict__ x, const float* __restrict__ W,
                           const float* __restrict__ a_src, const float* __restrict__ a_dst) {
    int idx = blockIdx.x * blockDim.x + threadIdx.x;
    if (idx >= NN * 32) return;
    int n = idx >> 5, p = idx & 31;
    float4 xr = *reinterpret_cast<const float4*>(x + n * 4);
    float s0 = xr.x * W[2 * p]       + xr.y * W[64 + 2 * p]
             + xr.z * W[128 + 2 * p] + xr.w * W[192 + 2 * p];
    float s1 = xr.x * W[2 * p + 1]       + xr.y * W[64 + 2 * p + 1]
             + xr.z * W[128 + 2 * p + 1] + xr.w * W[192 + 2 * p + 1];
    *reinterpret_cast<float2*>(g_h + n * 64 + 2 * p) = make_float2(s0, s1);
    g_hh[idx] = __floats2half2_rn(s0, s1);
    // fused score: head = p>>2, local feature = 2*(p&3)
    int head = p >> 2;
    int fl = 2 * (p & 3);
    float ps = s0 * a_src[head * 8 + fl] + s1 * a_src[head * 8 + fl + 1];
    float pd = s0 * a_dst[head * 8 + fl] + s1 * a_dst[head * 8 + fl + 1];
    ps += __shfl_xor_sync(0xffffffffu, ps, 1);
    ps += __shfl_xor_sync(0xffffffffu, ps, 2);
    pd += __shfl_xor_sync(0xffffffffu, pd, 1);
    pd += __shfl_xor_sync(0xffffffffu, pd, 2);
    if ((p & 3) == 0) {
        g_ssrc[n * 8 + head] = ps;
        g_sdst[n * 8 + head] = pd;
    }
}

// g_buf [N,64] @ W [64,64] -> g_h + g_hh + fused s (H=1, C=64).
// Block = 128 nodes, 256 threads, thread = 4 nodes x 8 feats.
// X tile: additive swizzle col'=(col+row)&63, conflict-free, 48KB smem exactly.
__global__ void gemm64_kernel(const float* __restrict__ W,
                              const float* __restrict__ a_src,
                              const float* __restrict__ a_dst) {
    __shared__ float Ws[64 * 64];
    __shared__ float Xs[128 * 64];
    int tx = threadIdx.x;
    int n0 = blockIdx.x * 128;
    const float4* W4p = reinterpret_cast<const float4*>(W);
    float4* Ws4 = reinterpret_cast<float4*>(Ws);
#pragma unroll
    for (int i = tx; i < 1024; i += 256) Ws4[i] = W4p[i];
    const float4* in4 = reinterpret_cast<const float4*>(g_buf);
#pragma unroll
    for (int i = tx; i < 2048; i += 256) {
        int r = i >> 4, c = i & 15;
        float4 v = make_float4(0.f, 0.f, 0.f, 0.f);
        if (n0 + r < NN) v = in4[(n0 + r) * 16 + c];
        Xs[r * 64 + ((4 * c + 0 + r) & 63)] = v.x;
        Xs[r * 64 + ((4 * c + 1 + r) & 63)] = v.y;
        Xs[r * 64 + ((4 * c + 2 + r) & 63)] = v.z;
        Xs[r * 64 + ((4 * c + 3 + r) & 63)] = v.w;
    }
    __syncthreads();
    int fg = tx & 7;    // feature group: f = fg*8 .. +7
    int ng = tx >> 3;   // node group: n = n0 + ng*4 .. +3
    float acc[4][8];
#pragma unroll
    for (int i = 0; i < 4; i++)
#pragma unroll
        for (int j = 0; j < 8; j++) acc[i][j] = 0.f;
#pragma unroll 8
    for (int k = 0; k < 64; k++) {
        float4 w0 = Ws4[k * 16 + fg * 2];
        float4 w1 = Ws4[k * 16 + fg * 2 + 1];
#pragma unroll
        for (int i = 0; i < 4; i++) {
            int row = ng * 4 + i;
            float xv = Xs[row * 64 + ((k + row) & 63)];
            acc[i][0] += xv * w0.x; acc[i][1] += xv * w0.y;
            acc[i][2] += xv * w0.z; acc[i][3] += xv * w0.w;
            acc[i][4] += xv * w1.x; acc[i][5] += xv * w1.y;
            acc[i][6] += xv * w1.z; acc[i][7] += xv * w1.w;
        }
    }
    // score weight chunk for this thread's 8 features
    float4 asA = *reinterpret_cast<const float4*>(a_src + fg * 8);
    float4 asB = *reinterpret_cast<const float4*>(a_src + fg * 8 + 4);
    float4 adA = *reinterpret_cast<const float4*>(a_dst + fg * 8);
    float4 adB = *reinterpret_cast<const float4*>(a_dst + fg * 8 + 4);
#pragma unroll
    for (int i = 0; i < 4; i++) {
        int n = n0 + ng * 4 + i;
        float ps = acc[i][0] * asA.x + acc[i][1] * asA.y + acc[i][2] * asA.z + acc[i][3] * asA.w
                 + acc[i][4] * asB.x + acc[i][5] * asB.y + acc[i][6] * asB.z + acc[i][7] * asB.w;
        float pd = acc[i][0] * adA.x + acc[i][1] * adA.y + acc[i][2] * adA.z + acc[i][3] * adA.w
                 + acc[i][4] * adB.x + acc[i][5] * adB.y + acc[i][6] * adB.z + acc[i][7] * adB.w;
        // reduce over the 8 lanes (same ng, fg=0..7) — consecutive lanes in warp
        ps += __shfl_xor_sync(0xffffffffu, ps, 1);
        ps += __shfl_xor_sync(0xffffffffu, ps, 2);
        ps += __shfl_xor_sync(0xffffffffu, ps, 4);
        pd += __shfl_xor_sync(0xffffffffu, pd, 1);
        pd += __shfl_xor_sync(0xffffffffu, pd, 2);
        pd += __shfl_xor_sync(0xffffffffu, pd, 4);
        if (n < NN) {
            float4* op = reinterpret_cast<float4*>(g_h + n * 64 + fg * 8);
            op[0] = make_float4(acc[i][0], acc[i][1], acc[i][2], acc[i][3]);
            op[1] = make_float4(acc[i][4], acc[i][5], acc[i][6], acc[i][7]);
            __half2* hh = g_hh + n * 32 + fg * 4;
            hh[0] = __floats2half2_rn(acc[i][0], acc[i][1]);
            hh[1] = __floats2half2_rn(acc[i][2], acc[i][3]);
            hh[2] = __floats2half2_rn(acc[i][4], acc[i][5]);
            hh[3] = __floats2half2_rn(acc[i][6], acc[i][7]);
            if (fg == 0) {
                g_ssrc[n] = ps;
                g_sdst[n] = pd;
            }
        }
    }
}

// conv4: g_buf [N,64] @ W [64,4] -> g_h4 + fused s (H=1, C=4). Warp per node.
__global__ void conv4_gemm(const float* __restrict__ W,
                           const float* __restrict__ a_src,
                           const float* __restrict__ a_dst) {
    int gtid = blockIdx.x * blockDim.x + threadIdx.x;
    int node = gtid >> 5;
    int lane = gtid & 31;
    if (node >= NN) return;
    float v0 = g_buf[node * 64 + lane];
    float v1 = g_buf[node * 64 + 32 + lane];
    float4 wA = reinterpret_cast<const float4*>(W)[lane];
    float4 wB = reinterpret_cast<const float4*>(W)[lane + 32];
    float p0 = v0 * wA.x + v1 * wB.x;
    float p1 = v0 * wA.y + v1 * wB.y;
    float p2 = v0 * wA.z + v1 * wB.z;
    float p3 = v0 * wA.w + v1 * wB.w;
#pragma unroll
    for (int off = 16; off > 0; off >>= 1) {
        p0 += __shfl_xor_sync(0xffffffffu, p0, off);
        p1 += __shfl_xor_sync(0xffffffffu, p1, off);
        p2 += __shfl_xor_sync(0xffffffffu, p2, off);
        p3 += __shfl_xor_sync(0xffffffffu, p3, off);
    }
    if (lane == 0) {
        float4* op = reinterpret_cast<float4*>(g_h4 + node * 4);
        *op = make_float4(p0, p1, p2, p3);
        g_ssrc[node] = p0 * a_src[0] + p1 * a_src[1] + p2 * a_src[2] + p3 * a_src[3];
        g_sdst[node] = p0 * a_dst[0] + p1 * a_dst[1] + p2 * a_dst[2] + p3 * a_dst[3];
    }
}

// ---------------- segment-softmax aggregation (CSR, warp-group per node) -------
// Layers 1-3 (FPL==2): gathers fp16 g_hh (4B/lane, 128B/edge). Layer 4: fp32.
// Edge loop unrolled x4 with batched loads (MLP).
template <int H, int C, int LPN, int FPL, bool DO_ELU, bool LAYER4>
__global__ void agg_kernel(const float* __restrict__ bias) {
    const int lane = threadIdx.x & 31;
    const int warp = (blockIdx.x * blockDim.x + threadIdx.x) >> 5;
    const int npw = 32 / LPN;
    const int node = warp * npw + lane / LPN;
    if (node >= NN) return;
    float* __restrict__ out = LAYER4 ? g_o4 : g_buf;
    const int gl = lane % LPN;
    const int f0 = gl * FPL;
    const int head = f0 / C;
    const float sd = g_sdst[node * H + head];
    const int rs = g_rowoff[node];
    const int re = g_rowoff[node + 1];
    float den = 0.f, a0 = 0.f, a1 = 0.f;
    int e = rs;
    for (; e + 4 <= re; e += 4) {
        int s0 = g_csr[e], s1 = g_csr[e + 1], s2 = g_csr[e + 2], s3 = g_csr[e + 3];
        float t0 = g_ssrc[s0 * H + head];
        float t1 = g_ssrc[s1 * H + head];
        float t2 = g_ssrc[s2 * H + head];
        float t3 = g_ssrc[s3 * H + head];
        float2 v0, v1, v2, v3;
        if (FPL == 2) {
            v0 = __half22float2(g_hh[s0 * 32 + gl]);
            v1 = __half22float2(g_hh[s1 * 32 + gl]);
            v2 = __half22float2(g_hh[s2 * 32 + gl]);
            v3 = __half22float2(g_hh[s3 * 32 + gl]);
        } else {
            v0.x = g_h4[s0 * (H * C) + f0]; v0.y = 0.f;
            v1.x = g_h4[s1 * (H * C) + f0]; v1.y = 0.f;
            v2.x = g_h4[s2 * (H * C) + f0]; v2.y = 0.f;
            v3.x = g_h4[s3 * (H * C) + f0]; v3.y = 0.f;
        }
        t0 += sd; t1 += sd; t2 += sd; t3 += sd;
        t0 = (t0 > 0.f) ? t0 : 0.2f * t0;
        t1 = (t1 > 0.f) ? t1 : 0.2f * t1;
        t2 = (t2 > 0.f) ? t2 : 0.2f * t2;
        t3 = (t3 > 0.f) ? t3 : 0.2f * t3;
        float e0 = __expf(t0), e1 = __expf(t1), e2 = __expf(t2), e3 = __expf(t3);
        den += (e0 + e1) + (e2 + e3);
        a0 += e0 * v0.x + e1 * v1.x + e2 * v2.x + e3 * v3.x;
        if (FPL == 2) a1 += e0 * v0.y + e1 * v1.y + e2 * v2.y + e3 * v3.y;
    }
    for (; e < re; ++e) {
        int src = g_csr[e];
        float s = g_ssrc[src * H + head] + sd;
        s = (s > 0.f) ? s : 0.2f * s;
        float ex = __expf(s);
        den += ex;
        if (FPL == 2) {
            float2 hv = __half22float2(g_hh[src * 32 + gl]);
            a0 += ex * hv.x;
            a1 += ex * hv.y;
        } else {
            a0 += ex * g_h4[src * (H * C) + f0];
        }
    }
    float inv = 1.f / (den + 1e-16f);
    float o0 = a0 * inv + bias[f0];
    if (DO_ELU) o0 = (o0 > 0.f) ? o0 : (__expf(o0) - 1.f);
    out[node * (H * C) + f0] = o0;
    if (FPL == 2) {
        float o1 = a1 * inv + bias[f0 + 1];
        if (DO_ELU) o1 = (o1 > 0.f) ? o1 : (__expf(o1) - 1.f);
        out[node * (H * C) + f0 + 1] = o1;
    }
}

// ---------------- pooling + head ----------------
__global__ void pool_kernel(const int* __restrict__ batch) {
    int i = blockIdx.x * blockDim.x + threadIdx.x;
    int lane = threadIdx.x & 31;
    int sh = g_shift;
    int g = -1;
    float v0 = 0.f, v1 = 0.f, v2 = 0.f, v3 = 0.f;
    if (i < NN) {
        g = batch[((long long)i) << sh];
        float4 hv = *reinterpret_cast<const float4*>(g_o4 + i * 4);
        v0 = hv.x; v1 = hv.y; v2 = hv.z; v3 = hv.w;
    }
    int g0 = __shfl_sync(0xffffffffu, g, 0);
    bool uniform = __all_sync(0xffffffffu, g == g0);
    if (uniform && g0 >= 0) {
#pragma unroll
        for (int off = 16; off > 0; off >>= 1) {
            v0 += __shfl_xor_sync(0xffffffffu, v0, off);
            v1 += __shfl_xor_sync(0xffffffffu, v1, off);
            v2 += __shfl_xor_sync(0xffffffffu, v2, off);
            v3 += __shfl_xor_sync(0xffffffffu, v3, off);
        }
        if (lane == 0) {
            atomicAdd(&g_pool[g0 * 4 + 0], v0);
            atomicAdd(&g_pool[g0 * 4 + 1], v1);
            atomicAdd(&g_pool[g0 * 4 + 2], v2);
            atomicAdd(&g_pool[g0 * 4 + 3], v3);
            atomicAdd(&g_cnt_g[g0], 32.f);
        }
    } else if (i < NN) {
        atomicAdd(&g_pool[g * 4 + 0], v0);
        atomicAdd(&g_pool[g * 4 + 1], v1);
        atomicAdd(&g_pool[g * 4 + 2], v2);
        atomicAdd(&g_pool[g * 4 + 3], v3);
        atomicAdd(&g_cnt_g[g], 1.f);
    }
}

__global__ void final_kernel(const float* __restrict__ Wl, const float* __restrict__ bl,
                             float* __restrict__ out) {
    int g = threadIdx.x;
    if (g >= GG) return;
    float c = fmaxf(g_cnt_g[g], 1.f);
    float s = 0.f;
#pragma unroll
    for (int f = 0; f < 4; f++) s += (g_pool[g * 4 + f] / c) * Wl[f];
    out[g] = s + bl[0];
}

// ---------------- launch ----------------
extern "C" void kernel_launch(void* const* d_in, const int* in_sizes, int n_in,
                              void* d_out, int out_size) {
    const float* x      = (const float*)d_in[0];
    const int*   ei     = (const int*)d_in[1];
    const int*   batch  = (const int*)d_in[2];
    const float* W1     = (const float*)d_in[3];
    const float* a_src1 = (const float*)d_in[4];
    const float* a_dst1 = (const float*)d_in[5];
    const float* b1     = (const float*)d_in[6];
    const float* W2     = (const float*)d_in[7];
    const float* a_src2 = (const float*)d_in[8];
    const float* a_dst2 = (const float*)d_in[9];
    const float* b2     = (const float*)d_in[10];
    const float* W4     = (const float*)d_in[11];
    const float* a_src4 = (const float*)d_in[12];
    const float* a_dst4 = (const float*)d_in[13];
    const float* b4     = (const float*)d_in[14];
    const float* Wl     = (const float*)d_in[15];
    const float* bl     = (const float*)d_in[16];
    float* out = (float*)d_out;

    const int B = 256;
    detect_kernel<<<1, 1024>>>((const unsigned int*)ei);
    // CSR build
    zero_kernel<<<(NN + B - 1) / B, B>>>();
    count_kernel<<<(ETOT + B - 1) / B, B>>>(ei);
    scan1_kernel<<<NB_SCAN, 1024>>>();
    scan2_kernel<<<1, 128>>>();
    scan3_kernel<<<(NN + B - 1) / B, B>>>();
    scatter_kernel<<<(ETOT + B - 1) / B, B>>>(ei);

    const int gridWarpPerNode = (NN * 32 + B - 1) / B;   // 12500

    // conv1 (H=8, C=8) + fused scores + ELU in agg
    conv1_gemm<<<(NN * 32 + B - 1) / B, B>>>(x, W1, a_src1, a_dst1);
    agg_kernel<8, 8, 32, 2, true, false><<<gridWarpPerNode, B>>>(b1);

    // conv2 (H=1, C=64), applied twice — scores fused into gemm epilogue
    gemm64_kernel<<<(NN + 127) / 128, B>>>(W2, a_src2, a_dst2);
    agg_kernel<1, 64, 32, 2, false, false><<<gridWarpPerNode, B>>>(b2);

    gemm64_kernel<<<(NN + 127) / 128, B>>>(W2, a_src2, a_dst2);
    agg_kernel<1, 64, 32, 2, false, false><<<gridWarpPerNode, B>>>(b2);

    // conv4 (H=1, C=4) + fused scores
    conv4_gemm<<<gridWarpPerNode, B>>>(W4, a_src4, a_dst4);
    agg_kernel<1, 4, 4, 1, false, true><<<(NN * 4 + B - 1) / B, B>>>(b4);

    // global mean pool + linear head
    pool_kernel<<<(NN + B - 1) / B, B>>>(batch);
    final_kernel<<<1, 64>>>(Wl, bl, out);
}

// round 9
// speedup vs baseline: 1.2456x; 1.0282x over previous
#include <cuda_runtime.h>
#include <cuda_fp16.h>
#include <cstdint>

#define NN   100000
#define EE   1600000
#define ETOT (EE + NN)
#define GG   64
#define NB_SCAN 98   // ceil(NN/1024)

// ---------------- scratch (device globals: no allocation allowed) ----------------
__device__ __align__(16) int   g_cnt[NN];
__device__ __align__(16) int   g_excl[NN];
__device__ __align__(16) int   g_bsum[128];
__device__ __align__(16) int   g_rowoff[NN + 1];
__device__ __align__(16) int   g_cur[NN];
__device__ __align__(16) int   g_csr[ETOT];

__device__ __align__(16) __half2 g_hh[NN * 32];    // fp16 h (edge gathers, layers 1-3)
__device__ __align__(16) __half2 g_bufh[NN * 32];  // fp16 conv output (next layer input)
__device__ __align__(16) float   g_ssrc[NN * 8];
__device__ __align__(16) float   g_sdst[NN * 8];
__device__ __align__(16) float   g_h4[NN * 4];
__device__ __align__(16) float   g_o4[NN * 4];
__device__ __align__(16) float   g_pool[GG * 4];
__device__ __align__(16) float   g_cnt_g[GG];
__device__ int g_shift;   // 0: indices are int32; 1: indices are int64 (read low words)

// ---------------- zero + dtype detection (merged) ----------------
__global__ void zero_detect_kernel(const unsigned int* __restrict__ w) {
    int i = blockIdx.x * blockDim.x + threadIdx.x;
    if (i < NN) g_cnt[i] = 0;
    if (i < GG * 4) g_pool[i] = 0.f;
    if (i < GG) g_cnt_g[i] = 0.f;
    if (blockIdx.x == 0) {
        __shared__ int any;
        if (threadIdx.x == 0) any = 0;
        __syncthreads();
        unsigned int acc = 0;
#pragma unroll
        for (int k = 0; k < 16; k++) {
            long long pos = 1LL + 2LL * ((long long)(threadIdx.x * 16 + k) * 391LL);
            if (pos < 2LL * EE) acc |= w[pos];
        }
        if (acc) atomicOr(&any, 1);
        __syncthreads();
        if (threadIdx.x == 0) g_shift = any ? 0 : 1;
    }
}

// ---------------- CSR build ----------------
__global__ void count_kernel(const int* __restrict__ ei) {
    int i = blockIdx.x * blockDim.x + threadIdx.x;
    if (i >= ETOT) return;
    int sh = g_shift;
    int dst = (i < EE) ? ei[((long long)(EE + i)) << sh] : (i - EE);
    atomicAdd(&g_cnt[dst], 1);
}

__global__ void scan1_kernel() {
    __shared__ int shm[1024];
    int tid = threadIdx.x;
    int gid = blockIdx.x * 1024 + tid;
    int v = (gid < NN) ? g_cnt[gid] : 0;
    shm[tid] = v;
    __syncthreads();
#pragma unroll
    for (int off = 1; off < 1024; off <<= 1) {
        int t = (tid >= off) ? shm[tid - off] : 0;
        __syncthreads();
        shm[tid] += t;
        __syncthreads();
    }
    if (gid < NN) g_excl[gid] = shm[tid] - v;
    if (tid == 1023) g_bsum[blockIdx.x] = shm[tid];
}

__global__ void scan2_kernel() {
    __shared__ int shm[128];
    int tid = threadIdx.x;
    int v = (tid < NB_SCAN) ? g_bsum[tid] : 0;
    shm[tid] = v;
    __syncthreads();
#pragma unroll
    for (int off = 1; off < 128; off <<= 1) {
        int t = (tid >= off) ? shm[tid - off] : 0;
        __syncthreads();
        shm[tid] += t;
        __syncthreads();
    }
    g_bsum[tid] = shm[tid] - v;  // exclusive
}

__global__ void scan3_kernel() {
    int gid = blockIdx.x * blockDim.x + threadIdx.x;
    if (gid < NN) {
        int off = g_excl[gid] + g_bsum[gid >> 10];
        g_rowoff[gid] = off;
        g_cur[gid]    = off;
    }
    if (gid == 0) g_rowoff[NN] = ETOT;
}

__global__ void scatter_kernel(const int* __restrict__ ei) {
    int i = blockIdx.x * blockDim.x + threadIdx.x;
    if (i >= ETOT) return;
    int sh = g_shift;
    int src, dst;
    if (i < EE) {
        src = ei[((long long)i) << sh];
        dst = ei[((long long)(EE + i)) << sh];
    } else {
        src = dst = i - EE;
    }
    int p = atomicAdd(&g_cur[dst], 1);
    g_csr[p] = src;
}

// ---------------- GEMMs (fused score epilogues; fp16 outputs) ----------------
// conv1: [N,4] @ [4,64] -> g_hh + fused s_src/s_dst (H=8, C=8).
__global__ void conv1_gemm(const float* __restrict__ x, const float* __restrict__ W,
                           const float* __restrict__ a_src, const float* __restrict__ a_dst) {
    int idx = blockIdx.x * blockDim.x + threadIdx.x;
    if (idx >= NN * 32) return;
    int n = idx >> 5, p = idx & 31;
    float4 xr = *reinterpret_cast<const float4*>(x + n * 4);
    float s0 = xr.x * W[2 * p]       + xr.y * W[64 + 2 * p]
             + xr.z * W[128 + 2 * p] + xr.w * W[192 + 2 * p];
    float s1 = xr.x * W[2 * p + 1]       + xr.y * W[64 + 2 * p + 1]
             + xr.z * W[128 + 2 * p + 1] + xr.w * W[192 + 2 * p + 1];
    g_hh[idx] = __floats2half2_rn(s0, s1);
    int head = p >> 2;
    int fl = 2 * (p & 3);
    float ps = s0 * a_src[head * 8 + fl] + s1 * a_src[head * 8 + fl + 1];
    float pd = s0 * a_dst[head * 8 + fl] + s1 * a_dst[head * 8 + fl + 1];
    ps += __shfl_xor_sync(0xffffffffu, ps, 1);
    ps += __shfl_xor_sync(0xffffffffu, ps, 2);
    pd += __shfl_xor_sync(0xffffffffu, pd, 1);
    pd += __shfl_xor_sync(0xffffffffu, pd, 2);
    if ((p & 3) == 0) {
        g_ssrc[n * 8 + head] = ps;
        g_sdst[n * 8 + head] = pd;
    }
}

// g_bufh [N,64]h @ W [64,64] -> g_hh + fused s (H=1, C=64).
// Block = 128 nodes, 256 threads, thread = 4 nodes x 8 feats.
// X tile: additive swizzle col'=(col+row)&63, conflict-free, 48KB smem exactly.
__global__ void gemm64_kernel(const float* __restrict__ W,
                              const float* __restrict__ a_src,
                              const float* __restrict__ a_dst) {
    __shared__ float Ws[64 * 64];
    __shared__ float Xs[128 * 64];
    int tx = threadIdx.x;
    int n0 = blockIdx.x * 128;
    const float4* W4p = reinterpret_cast<const float4*>(W);
    float4* Ws4 = reinterpret_cast<float4*>(Ws);
#pragma unroll
    for (int i = tx; i < 1024; i += 256) Ws4[i] = W4p[i];
    const uint4* bh4 = reinterpret_cast<const uint4*>(g_bufh);
#pragma unroll
    for (int i = tx; i < 1024; i += 256) {
        int r = i >> 3, c = i & 7;       // 8 uint4 (64 halves) per node row
        uint4 raw = make_uint4(0u, 0u, 0u, 0u);
        if (n0 + r < NN) raw = bh4[(n0 + r) * 8 + c];
        const __half2* hp = reinterpret_cast<const __half2*>(&raw);
#pragma unroll
        for (int j = 0; j < 4; j++) {
            float2 f = __half22float2(hp[j]);
            Xs[r * 64 + ((8 * c + 2 * j + 0 + r) & 63)] = f.x;
            Xs[r * 64 + ((8 * c + 2 * j + 1 + r) & 63)] = f.y;
        }
    }
    __syncthreads();
    int fg = tx & 7;    // feature group: f = fg*8 .. +7
    int ng = tx >> 3;   // node group: n = n0 + ng*4 .. +3
    float acc[4][8];
#pragma unroll
    for (int i = 0; i < 4; i++)
#pragma unroll
        for (int j = 0; j < 8; j++) acc[i][j] = 0.f;
#pragma unroll 8
    for (int k = 0; k < 64; k++) {
        float4 w0 = Ws4[k * 16 + fg * 2];
        float4 w1 = Ws4[k * 16 + fg * 2 + 1];
#pragma unroll
        for (int i = 0; i < 4; i++) {
            int row = ng * 4 + i;
            float xv = Xs[row * 64 + ((k + row) & 63)];
            acc[i][0] += xv * w0.x; acc[i][1] += xv * w0.y;
            acc[i][2] += xv * w0.z; acc[i][3] += xv * w0.w;
            acc[i][4] += xv * w1.x; acc[i][5] += xv * w1.y;
            acc[i][6] += xv * w1.z; acc[i][7] += xv * w1.w;
        }
    }
    float4 asA = *reinterpret_cast<const float4*>(a_src + fg * 8);
    float4 asB = *reinterpret_cast<const float4*>(a_src + fg * 8 + 4);
    float4 adA = *reinterpret_cast<const float4*>(a_dst + fg * 8);
    float4 adB = *reinterpret_cast<const float4*>(a_dst + fg * 8 + 4);
#pragma unroll
    for (int i = 0; i < 4; i++) {
        int n = n0 + ng * 4 + i;
        float ps = acc[i][0] * asA.x + acc[i][1] * asA.y + acc[i][2] * asA.z + acc[i][3] * asA.w
                 + acc[i][4] * asB.x + acc[i][5] * asB.y + acc[i][6] * asB.z + acc[i][7] * asB.w;
        float pd = acc[i][0] * adA.x + acc[i][1] * adA.y + acc[i][2] * adA.z + acc[i][3] * adA.w
                 + acc[i][4] * adB.x + acc[i][5] * adB.y + acc[i][6] * adB.z + acc[i][7] * adB.w;
        ps += __shfl_xor_sync(0xffffffffu, ps, 1);
        ps += __shfl_xor_sync(0xffffffffu, ps, 2);
        ps += __shfl_xor_sync(0xffffffffu, ps, 4);
        pd += __shfl_xor_sync(0xffffffffu, pd, 1);
        pd += __shfl_xor_sync(0xffffffffu, pd, 2);
        pd += __shfl_xor_sync(0xffffffffu, pd, 4);
        if (n < NN) {
            __half2* hh = g_hh + n * 32 + fg * 4;
            hh[0] = __floats2half2_rn(acc[i][0], acc[i][1]);
            hh[1] = __floats2half2_rn(acc[i][2], acc[i][3]);
            hh[2] = __floats2half2_rn(acc[i][4], acc[i][5]);
            hh[3] = __floats2half2_rn(acc[i][6], acc[i][7]);
            if (fg == 0) {
                g_ssrc[n] = ps;
                g_sdst[n] = pd;
            }
        }
    }
}

// conv4: g_bufh [N,64]h @ W [64,4] -> g_h4 + fused s (H=1, C=4). Warp per node.
// Lane owns features 2l, 2l+1.
__global__ void conv4_gemm(const float* __restrict__ W,
                           const float* __restrict__ a_src,
                           const float* __restrict__ a_dst) {
    int gtid = blockIdx.x * blockDim.x + threadIdx.x;
    int node = gtid >> 5;
    int lane = gtid & 31;
    if (node >= NN) return;
    float2 hv = __half22float2(g_bufh[node * 32 + lane]);
    float4 wA = reinterpret_cast<const float4*>(W)[2 * lane];
    float4 wB = reinterpret_cast<const float4*>(W)[2 * lane + 1];
    float p0 = hv.x * wA.x + hv.y * wB.x;
    float p1 = hv.x * wA.y + hv.y * wB.y;
    float p2 = hv.x * wA.z + hv.y * wB.z;
    float p3 = hv.x * wA.w + hv.y * wB.w;
#pragma unroll
    for (int off = 16; off > 0; off >>= 1) {
        p0 += __shfl_xor_sync(0xffffffffu, p0, off);
        p1 += __shfl_xor_sync(0xffffffffu, p1, off);
        p2 += __shfl_xor_sync(0xffffffffu, p2, off);
        p3 += __shfl_xor_sync(0xffffffffu, p3, off);
    }
    if (lane == 0) {
        float4* op = reinterpret_cast<float4*>(g_h4 + node * 4);
        *op = make_float4(p0, p1, p2, p3);
        g_ssrc[node] = p0 * a_src[0] + p1 * a_src[1] + p2 * a_src[2] + p3 * a_src[3];
        g_sdst[node] = p0 * a_dst[0] + p1 * a_dst[1] + p2 * a_dst[2] + p3 * a_dst[3];
    }
}

// ---------------- segment-softmax aggregation (CSR, warp-group per node) -------
// Layers 1-3 (FPL==2): gather fp16 g_hh, write fp16 g_bufh. Layer 4: fp32.
// Edge loop: scalar prologue to 4-alignment, then x4 with int4 CSR loads.
template <int H, int C, int LPN, int FPL, bool DO_ELU, bool LAYER4>
__global__ void agg_kernel(const float* __restrict__ bias) {
    const int lane = threadIdx.x & 31;
    const int warp = (blockIdx.x * blockDim.x + threadIdx.x) >> 5;
    const int npw = 32 / LPN;
    const int node = warp * npw + lane / LPN;
    if (node >= NN) return;
    const int gl = lane % LPN;
    const int f0 = gl * FPL;
    const int head = f0 / C;
    const float sd = g_sdst[node * H + head];
    const int rs = g_rowoff[node];
    const int re = g_rowoff[node + 1];
    float den = 0.f, a0 = 0.f, a1 = 0.f;
    int e = rs;
    // scalar prologue to 16B alignment
    for (; e < re && (e & 3); ++e) {
        int src = g_csr[e];
        float s = g_ssrc[src * H + head] + sd;
        s = (s > 0.f) ? s : 0.2f * s;
        float ex = __expf(s);
        den += ex;
        if (FPL == 2) {
            float2 hv = __half22float2(g_hh[src * 32 + gl]);
            a0 += ex * hv.x;
            a1 += ex * hv.y;
        } else {
            a0 += ex * g_h4[src * (H * C) + f0];
        }
    }
    for (; e + 4 <= re; e += 4) {
        int4 cs = *reinterpret_cast<const int4*>(g_csr + e);
        float t0 = g_ssrc[cs.x * H + head];
        float t1 = g_ssrc[cs.y * H + head];
        float t2 = g_ssrc[cs.z * H + head];
        float t3 = g_ssrc[cs.w * H + head];
        float2 v0, v1, v2, v3;
        if (FPL == 2) {
            v0 = __half22float2(g_hh[cs.x * 32 + gl]);
            v1 = __half22float2(g_hh[cs.y * 32 + gl]);
            v2 = __half22float2(g_hh[cs.z * 32 + gl]);
            v3 = __half22float2(g_hh[cs.w * 32 + gl]);
        } else {
            v0.x = g_h4[cs.x * (H * C) + f0]; v0.y = 0.f;
            v1.x = g_h4[cs.y * (H * C) + f0]; v1.y = 0.f;
            v2.x = g_h4[cs.z * (H * C) + f0]; v2.y = 0.f;
            v3.x = g_h4[cs.w * (H * C) + f0]; v3.y = 0.f;
        }
        t0 += sd; t1 += sd; t2 += sd; t3 += sd;
        t0 = (t0 > 0.f) ? t0 : 0.2f * t0;
        t1 = (t1 > 0.f) ? t1 : 0.2f * t1;
        t2 = (t2 > 0.f) ? t2 : 0.2f * t2;
        t3 = (t3 > 0.f) ? t3 : 0.2f * t3;
        float e0 = __expf(t0), e1 = __expf(t1), e2 = __expf(t2), e3 = __expf(t3);
        den += (e0 + e1) + (e2 + e3);
        a0 += e0 * v0.x + e1 * v1.x + e2 * v2.x + e3 * v3.x;
        if (FPL == 2) a1 += e0 * v0.y + e1 * v1.y + e2 * v2.y + e3 * v3.y;
    }
    for (; e < re; ++e) {
        int src = g_csr[e];
        float s = g_ssrc[src * H + head] + sd;
        s = (s > 0.f) ? s : 0.2f * s;
        float ex = __expf(s);
        den += ex;
        if (FPL == 2) {
            float2 hv = __half22float2(g_hh[src * 32 + gl]);
            a0 += ex * hv.x;
            a1 += ex * hv.y;
        } else {
            a0 += ex * g_h4[src * (H * C) + f0];
        }
    }
    float inv = 1.f / (den + 1e-16f);
    float o0 = a0 * inv + bias[f0];
    if (DO_ELU) o0 = (o0 > 0.f) ? o0 : (__expf(o0) - 1.f);
    if (FPL == 2) {
        float o1 = a1 * inv + bias[f0 + 1];
        if (DO_ELU) o1 = (o1 > 0.f) ? o1 : (__expf(o1) - 1.f);
        g_bufh[node * 32 + gl] = __floats2half2_rn(o0, o1);
    } else {
        g_o4[node * (H * C) + f0] = o0;
    }
}

// ---------------- pooling + head ----------------
__global__ void pool_kernel(const int* __restrict__ batch) {
    int i = blockIdx.x * blockDim.x + threadIdx.x;
    int lane = threadIdx.x & 31;
    int sh = g_shift;
    int g = -1;
    float v0 = 0.f, v1 = 0.f, v2 = 0.f, v3 = 0.f;
    if (i < NN) {
        g = batch[((long long)i) << sh];
        float4 hv = *reinterpret_cast<const float4*>(g_o4 + i * 4);
        v0 = hv.x; v1 = hv.y; v2 = hv.z; v3 = hv.w;
    }
    int g0 = __shfl_sync(0xffffffffu, g, 0);
    bool uniform = __all_sync(0xffffffffu, g == g0);
    if (uniform && g0 >= 0) {
#pragma unroll
        for (int off = 16; off > 0; off >>= 1) {
            v0 += __shfl_xor_sync(0xffffffffu, v0, off);
            v1 += __shfl_xor_sync(0xffffffffu, v1, off);
            v2 += __shfl_xor_sync(0xffffffffu, v2, off);
            v3 += __shfl_xor_sync(0xffffffffu, v3, off);
        }
        if (lane == 0) {
            atomicAdd(&g_pool[g0 * 4 + 0], v0);
            atomicAdd(&g_pool[g0 * 4 + 1], v1);
            atomicAdd(&g_pool[g0 * 4 + 2], v2);
            atomicAdd(&g_pool[g0 * 4 + 3], v3);
            atomicAdd(&g_cnt_g[g0], 32.f);
        }
    } else if (i < NN) {
        atomicAdd(&g_pool[g * 4 + 0], v0);
        atomicAdd(&g_pool[g * 4 + 1], v1);
        atomicAdd(&g_pool[g * 4 + 2], v2);
        atomicAdd(&g_pool[g * 4 + 3], v3);
        atomicAdd(&g_cnt_g[g], 1.f);
    }
}

__global__ void final_kernel(const float* __restrict__ Wl, const float* __restrict__ bl,
                             float* __restrict__ out) {
    int g = threadIdx.x;
    if (g >= GG) return;
    float c = fmaxf(g_cnt_g[g], 1.f);
    float s = 0.f;
#pragma unroll
    for (int f = 0; f < 4; f++) s += (g_pool[g * 4 + f] / c) * Wl[f];
    out[g] = s + bl[0];
}

// ---------------- launch ----------------
extern "C" void kernel_launch(void* const* d_in, const int* in_sizes, int n_in,
                              void* d_out, int out_size) {
    const float* x      = (const float*)d_in[0];
    const int*   ei     = (const int*)d_in[1];
    const int*   batch  = (const int*)d_in[2];
    const float* W1     = (const float*)d_in[3];
    const float* a_src1 = (const float*)d_in[4];
    const float* a_dst1 = (const float*)d_in[5];
    const float* b1     = (const float*)d_in[6];
    const float* W2     = (const float*)d_in[7];
    const float* a_src2 = (const float*)d_in[8];
    const float* a_dst2 = (const float*)d_in[9];
    const float* b2     = (const float*)d_in[10];
    const float* W4     = (const float*)d_in[11];
    const float* a_src4 = (const float*)d_in[12];
    const float* a_dst4 = (const float*)d_in[13];
    const float* b4     = (const float*)d_in[14];
    const float* Wl     = (const float*)d_in[15];
    const float* bl     = (const float*)d_in[16];
    float* out = (float*)d_out;

    const int B = 256;
    zero_detect_kernel<<<(NN + B - 1) / B, B>>>((const unsigned int*)ei);
    count_kernel<<<(ETOT + B - 1) / B, B>>>(ei);
    scan1_kernel<<<NB_SCAN, 1024>>>();
    scan2_kernel<<<1, 128>>>();
    scan3_kernel<<<(NN + B - 1) / B, B>>>();
    scatter_kernel<<<(ETOT + B - 1) / B, B>>>(ei);

    const int gridWarpPerNode = (NN * 32 + B - 1) / B;   // 12500

    // conv1 (H=8, C=8) + fused scores; ELU in agg
    conv1_gemm<<<(NN * 32 + B - 1) / B, B>>>(x, W1, a_src1, a_dst1);
    agg_kernel<8, 8, 32, 2, true, false><<<gridWarpPerNode, B>>>(b1);

    // conv2 (H=1, C=64), applied twice — scores fused into gemm epilogue
    gemm64_kernel<<<(NN + 127) / 128, B>>>(W2, a_src2, a_dst2);
    agg_kernel<1, 64, 32, 2, false, false><<<gridWarpPerNode, B>>>(b2);

    gemm64_kernel<<<(NN + 127) / 128, B>>>(W2, a_src2, a_dst2);
    agg_kernel<1, 64, 32, 2, false, false><<<gridWarpPerNode, B>>>(b2);

    // conv4 (H=1, C=4) + fused scores
    conv4_gemm<<<gridWarpPerNode, B>>>(W4, a_src4, a_dst4);
    agg_kernel<1, 4, 4, 1, false, true><<<(NN * 4 + B - 1) / B, B>>>(b4);

    // global mean pool + linear head
    pool_kernel<<<(NN + B - 1) / B, B>>>(batch);
    final_kernel<<<1, 64>>>(Wl, bl, out);
}